// round 8
// baseline (speedup 1.0000x reference)
#include <cuda_runtime.h>
#include <cuda_bf16.h>
#include <cstdint>
#include <math.h>

// ---------------- problem constants ----------------
#define U_N   10000
#define G_N   3000
#define I_N   8000
#define B_N   4096
#define LM    20

// ---------------- scratch layout (floats) ----------------
// Zero-init region [0, 3936000) is one contiguous block -> single zero kernel.
constexpr int OFF_UI_A = 0;        // 576000  UI layer2 (l2) output
constexpr int OFF_UI_B = 576000;   // 576000  UI layer1 (l1) output
constexpr int OFF_UI_C = 1152000;  // 576000  UI layer3 (l3) output
constexpr int OFF_GI_A = 1728000;  // 352000  GI l2
constexpr int OFF_GI_B = 2080000;  // 352000  GI l1
constexpr int OFF_GI_C = 2432000;  // 352000  GI l3
constexpr int OFF_YS   = 2784000;  // 320000  user social term 1
constexpr int OFF_UM   = 3104000;  // 320000  user social term 2
constexpr int OFF_YI   = 3424000;  // 256000  item social term 1
constexpr int OFF_IM   = 3680000;  // 256000  item social term 2
// end of zeroed region (3936000)
constexpr int OFF_USUM = 3936000;  // 320000  sum of 4 UI user layers (unscaled)
constexpr int OFF_IEU  = 4256000;  // 256000  item_emb_for_user (0.25 * item sum)
constexpr int OFF_GIIS = 4512000;  // 256000  sum of 4 GI item layers (unscaled)
constexpr int OFF_GSUM = 4768000;  // 96000   gemb + odd g_layers (l2 part added later)
constexpr int OFF_GUL  = 4864000;  // 96000
constexpr int OFF_W    = 4960000;  // 6400
constexpr int OFF_GF   = 4966400;  // 96000
constexpr int SCRATCH_TOTAL = 5062400;

__device__ float d_scratch[SCRATCH_TOTAL];

// ---------------- elementwise helpers ----------------
__global__ void k_zero4(float4* p, int n4) {
    int i = blockIdx.x * blockDim.x + threadIdx.x;
    if (i < n4) p[i] = make_float4(0.f, 0.f, 0.f, 0.f);
}

__device__ __forceinline__ float4 add4(float4 a, float4 b) {
    return make_float4(a.x+b.x, a.y+b.y, a.z+b.z, a.w+b.w);
}
__device__ __forceinline__ float4 mul4(float4 a, float s) {
    return make_float4(a.x*s, a.y*s, a.z*s, a.w*s);
}

// Combine UI layers: USUM (user rows, unscaled sum incl. emb), IEU = 0.25*item sum.
// Tail segment initializes GSUM = gemb.
__global__ void k_comb_ui(float* __restrict__ S, const float4* __restrict__ uemb,
                          const float4* __restrict__ iemb, const float4* __restrict__ gemb) {
    int i = blockIdx.x * blockDim.x + threadIdx.x;
    const float4* A = (const float4*)(S + OFF_UI_A);
    const float4* B = (const float4*)(S + OFF_UI_B);
    const float4* C = (const float4*)(S + OFF_UI_C);
    if (i < 80000) {
        float4 s = add4(add4(uemb[i], B[i]), add4(A[i], C[i]));
        ((float4*)(S + OFF_USUM))[i] = s;
    } else if (i < 144000) {
        int j = i - 80000;
        float4 s = add4(add4(iemb[j], B[i]), add4(A[i], C[i]));
        ((float4*)(S + OFF_IEU))[j] = mul4(s, 0.25f);
    } else if (i < 168000) {
        int j = i - 144000;
        ((float4*)(S + OFF_GSUM))[j] = gemb[j];
    }
}

// Combine GI item layers: GIIS = IEU + item parts of l1,l2,l3 (unscaled).
__global__ void k_comb_gi(float* __restrict__ S) {
    int i = blockIdx.x * blockDim.x + threadIdx.x;
    if (i >= 64000) return;
    int j = G_N * 8 + i;  // item rows start at G_N*32 floats = G_N*8 float4s
    const float4* A = (const float4*)(S + OFF_GI_A);
    const float4* B = (const float4*)(S + OFF_GI_B);
    const float4* C = (const float4*)(S + OFF_GI_C);
    const float4* E = (const float4*)(S + OFF_IEU);
    ((float4*)(S + OFF_GIIS))[i] = add4(add4(E[i], B[j]), add4(A[j], C[j]));
}

// ---------------- COO SpMM, warp-cooperative index loads ----------------
// Each warp handles 4 edges: lanes 0-11 load the 12 r/c/v scalars, shfl-broadcast.
__global__ void k_spmm(const int* __restrict__ rows, const int* __restrict__ cols,
                       const float* __restrict__ vals, int nnz,
                       const float* __restrict__ x0, const float* __restrict__ x1,
                       int split, float* __restrict__ out, int row_limit) {
    int gw = (blockIdx.x * blockDim.x + threadIdx.x) >> 5;
    int lane = threadIdx.x & 31;
    int e0 = gw << 2;
    if (e0 >= nnz) return;
    int ld = 0;
    int which = lane >> 2;              // 0:rows 1:cols 2:vals
    int j4 = e0 + (lane & 3);
    if (j4 < nnz) {
        if (which == 0)      ld = __ldg(rows + j4);
        else if (which == 1) ld = __ldg(cols + j4);
        else if (which == 2) ld = __float_as_int(__ldg(vals + j4));
    }
    int sub = lane >> 3;                // which of the 4 edges
    int l4  = (lane & 7) << 2;          // float4 slot within row
    int e = e0 + sub;
    int r =                 __shfl_sync(0xffffffffu, ld, sub);
    int c =                 __shfl_sync(0xffffffffu, ld, 4 + sub);
    float v = __int_as_float(__shfl_sync(0xffffffffu, ld, 8 + sub));
    if (e >= nnz || r >= row_limit) return;
    const float* src = (c < split) ? (x0 + ((size_t)c << 5))
                                   : (x1 + ((size_t)(c - split) << 5));
    float4 xv = *(const float4*)(src + l4);
    asm volatile("red.global.add.v4.f32 [%0], {%1, %2, %3, %4};"
                 :: "l"(out + ((size_t)r << 5) + l4),
                    "f"(v*xv.x), "f"(v*xv.y), "f"(v*xv.z), "f"(v*xv.w) : "memory");
}

// ---------------- tensor-core dense MM, two fused problems ----------------
#define MMKC 32
#define MALD 40

__device__ __forceinline__ uint32_t cvta_s(const void* p) {
    return (uint32_t)__cvta_generic_to_shared(p);
}
__device__ __forceinline__ void ldm_x4(uint32_t* r, uint32_t addr) {
    asm volatile("ldmatrix.sync.aligned.m8n8.x4.shared.b16 {%0,%1,%2,%3}, [%4];"
                 : "=r"(r[0]), "=r"(r[1]), "=r"(r[2]), "=r"(r[3]) : "r"(addr));
}
__device__ __forceinline__ void ldm_x4_t(uint32_t* r, uint32_t addr) {
    asm volatile("ldmatrix.sync.aligned.m8n8.x4.trans.shared.b16 {%0,%1,%2,%3}, [%4];"
                 : "=r"(r[0]), "=r"(r[1]), "=r"(r[2]), "=r"(r[3]) : "r"(addr));
}
__device__ __forceinline__ void mma_bf16(float* d, const uint32_t* a,
                                         uint32_t b0, uint32_t b1) {
    asm volatile("mma.sync.aligned.m16n8k16.row.col.f32.bf16.bf16.f32 "
                 "{%0,%1,%2,%3}, {%4,%5,%6,%7}, {%8,%9}, {%0,%1,%2,%3};"
                 : "+f"(d[0]), "+f"(d[1]), "+f"(d[2]), "+f"(d[3])
                 : "r"(a[0]), "r"(a[1]), "r"(a[2]), "r"(a[3]), "r"(b0), "r"(b1));
}
__device__ __forceinline__ void red2(float* p, float a, float b) {
    asm volatile("red.global.add.v2.f32 [%0], {%1, %2};"
                 :: "l"(p), "f"(a), "f"(b) : "memory");
}
__device__ __forceinline__ void st_split4(float4 v, __nv_bfloat16* hd, __nv_bfloat16* ldst) {
    uint32_t x0 = __float_as_uint(v.x), x1 = __float_as_uint(v.y);
    uint32_t x2 = __float_as_uint(v.z), x3 = __float_as_uint(v.w);
    uint32_t h01, h23;
    asm("prmt.b32 %0, %1, %2, 0x7632;" : "=r"(h01) : "r"(x0), "r"(x1));
    asm("prmt.b32 %0, %1, %2, 0x7632;" : "=r"(h23) : "r"(x2), "r"(x3));
    float l0 = v.x - __uint_as_float(x0 & 0xFFFF0000u);
    float l1 = v.y - __uint_as_float(x1 & 0xFFFF0000u);
    float l2 = v.z - __uint_as_float(x2 & 0xFFFF0000u);
    float l3 = v.w - __uint_as_float(x3 & 0xFFFF0000u);
    uint32_t lo01, lo23;
    asm("prmt.b32 %0, %1, %2, 0x7632;" : "=r"(lo01)
        : "r"(__float_as_uint(l0)), "r"(__float_as_uint(l1)));
    asm("prmt.b32 %0, %1, %2, 0x7632;" : "=r"(lo23)
        : "r"(__float_as_uint(l2)), "r"(__float_as_uint(l3)));
    *(uint2*)hd   = make_uint2(h01, h23);
    *(uint2*)ldst = make_uint2(lo01, lo23);
}

__global__ void __launch_bounds__(256, 4)
k_mm_tc2(const float* __restrict__ A0, const float* __restrict__ x0f,
         float* __restrict__ y0, int n0, int gx0,
         const float* __restrict__ A1, const float* __restrict__ x1f,
         float* __restrict__ y1, int n1) {
    __shared__ __nv_bfloat16 Ah[128 * MALD], Al[128 * MALD];
    __shared__ __nv_bfloat16 Xh[MMKC * MALD], Xl[MMKC * MALD];
    int tid = threadIdx.x;
    int warp = tid >> 5, lane = tid & 31;

    int bx = blockIdx.x;
    const float *A, *x; float* y; int n;
    if (bx < gx0) { A = A0; x = x0f; y = y0; n = n0; }
    else          { A = A1; x = x1f; y = y1; n = n1; bx -= gx0; }
    int m0 = bx * 128;

    int nchunks = (n + MMKC - 1) / MMKC;
    int per = (nchunks + gridDim.y - 1) / gridDim.y;
    int ci0 = blockIdx.y * per;
    int ci1 = min(nchunks, ci0 + per);

    float acc[4][4];
    #pragma unroll
    for (int f = 0; f < 4; f++)
        #pragma unroll
        for (int j = 0; j < 4; j++) acc[f][j] = 0.f;

    uint32_t aAddrH = cvta_s(&Ah[(warp * 16 + (lane & 15)) * MALD + ((lane >> 4) << 3)]);
    uint32_t aAddrL = cvta_s(&Al[(warp * 16 + (lane & 15)) * MALD + ((lane >> 4) << 3)]);
    uint32_t xBaseH = cvta_s(&Xh[(lane & 15) * MALD + ((lane >> 4) << 3)]);
    uint32_t xBaseL = cvta_s(&Xl[(lane & 15) * MALD + ((lane >> 4) << 3)]);

    int ar = tid >> 1, ahalf = tid & 1;
    int xr = tid >> 3, xc = (tid & 7) << 2;
    int gr = m0 + ar;
    const float* Arow = A + (size_t)gr * n + ahalf * 16;

    float4 aR[4], xR;
    const float4 Z4 = make_float4(0.f, 0.f, 0.f, 0.f);
    {
        int k0 = ci0 * MMKC;
        xR = Z4;
        if (k0 + xr < n) xR = *(const float4*)(x + (size_t)(k0 + xr) * 32 + xc);
        #pragma unroll
        for (int j = 0; j < 4; j++) {
            int col = ahalf * 16 + j * 4;
            aR[j] = Z4;
            if (gr < n && (k0 + col + 4) <= n) aR[j] = *(const float4*)(Arow + k0 + j * 4);
        }
    }

    for (int ci = ci0; ci < ci1; ci++) {
        st_split4(xR, &Xh[xr * MALD + xc], &Xl[xr * MALD + xc]);
        #pragma unroll
        for (int j = 0; j < 4; j++) {
            int col = ahalf * 16 + j * 4;
            st_split4(aR[j], &Ah[ar * MALD + col], &Al[ar * MALD + col]);
        }
        __syncthreads();
        if (ci + 1 < ci1) {
            int k0 = (ci + 1) * MMKC;
            xR = Z4;
            if (k0 + xr < n) xR = *(const float4*)(x + (size_t)(k0 + xr) * 32 + xc);
            #pragma unroll
            for (int j = 0; j < 4; j++) {
                int col = ahalf * 16 + j * 4;
                aR[j] = Z4;
                if (gr < n && (k0 + col + 4) <= n) aR[j] = *(const float4*)(Arow + k0 + j * 4);
            }
        }
        #pragma unroll
        for (int ks = 0; ks < MMKC; ks += 16) {
            uint32_t afh[4], afl[4];
            ldm_x4(afh, aAddrH + ks * 2);
            ldm_x4(afl, aAddrL + ks * 2);
            #pragma unroll
            for (int np = 0; np < 2; np++) {
                uint32_t bh[4], bl[4];
                uint32_t off = (uint32_t)(ks * MALD + np * 16) * 2;
                ldm_x4_t(bh, xBaseH + off);
                ldm_x4_t(bl, xBaseL + off);
                mma_bf16(acc[np * 2 + 0], afh, bh[0], bh[1]);
                mma_bf16(acc[np * 2 + 1], afh, bh[2], bh[3]);
                mma_bf16(acc[np * 2 + 0], afh, bl[0], bl[1]);
                mma_bf16(acc[np * 2 + 1], afh, bl[2], bl[3]);
                mma_bf16(acc[np * 2 + 0], afl, bh[0], bh[1]);
                mma_bf16(acc[np * 2 + 1], afl, bh[2], bh[3]);
            }
        }
        __syncthreads();
    }

    int gr8 = lane >> 2, cc = (lane & 3) * 2;
    #pragma unroll
    for (int f = 0; f < 4; f++) {
        int nc = f * 8 + cc;
        int r0 = m0 + warp * 16 + gr8;
        int r1 = r0 + 8;
        if (r0 < n) red2(y + (size_t)r0 * 32 + nc, acc[f][0], acc[f][1]);
        if (r1 < n) red2(y + (size_t)r1 * 32 + nc, acc[f][2], acc[f][3]);
    }
}

// ---------------- group_userlayer: pool over 0.25*(usum+ys+um) ----------------
__global__ void k_gul(float* __restrict__ gul, const int* __restrict__ users,
                      const float* __restrict__ mask, const float* __restrict__ t0,
                      const float* __restrict__ t1, const float* __restrict__ t2) {
    int i = blockIdx.x * blockDim.x + threadIdx.x;
    if (i >= G_N * 32) return;
    int g = i >> 5, d = i & 31;
    float s = 0.f;
    #pragma unroll
    for (int l = 0; l < LM; l++) {
        int u = __ldg(users + g * LM + l);
        size_t o = ((size_t)u << 5) + d;
        float acc = __ldg(t0 + o) + __ldg(t1 + o) + __ldg(t2 + o);
        s = fmaf(__ldg(mask + g * LM + l), acc, s);
    }
    gul[i] = 0.25f * s;
}

// ---------------- gate MLP (one warp per row); g_emb = 0.25*(gsum+gl2) ----------------
__global__ void k_gate(float* __restrict__ w, const float* __restrict__ gsum,
                       const float* __restrict__ gl2, const float* __restrict__ gul,
                       const float* __restrict__ w1, const float* __restrict__ b1,
                       const float* __restrict__ w2, const float* __restrict__ b2) {
    int wid = (blockIdx.x * blockDim.x + threadIdx.x) >> 5;
    int lane = threadIdx.x & 31;
    if (wid >= 2 * G_N) return;
    float xd;
    if (wid < G_N) {
        size_t o = (size_t)wid * 32 + lane;
        xd = 0.25f * (__ldg(gsum + o) + __ldg(gl2 + o));
    } else {
        xd = __ldg(gul + (size_t)(wid - G_N) * 32 + lane);
    }
    float h = b1[lane];
    #pragma unroll
    for (int d = 0; d < 32; d++) {
        float a = __shfl_sync(0xffffffffu, xd, d);
        h = fmaf(a, __ldg(w1 + d * 32 + lane), h);
    }
    h = fmaxf(h, 0.f);
    float t = h * __ldg(w2 + lane);
    #pragma unroll
    for (int o = 16; o > 0; o >>= 1) t += __shfl_xor_sync(0xffffffffu, t, o);
    if (lane == 0) w[wid] = 1.f / (1.f + expf(-(t + b2[0])));
}

__global__ void k_combine(float* __restrict__ gf, const float* __restrict__ w,
                          const float* __restrict__ gsum, const float* __restrict__ gl2,
                          const float* __restrict__ gul) {
    int i = blockIdx.x * blockDim.x + threadIdx.x;
    if (i >= G_N * 32) return;
    int g = i >> 5;
    gf[i] = w[g] * 0.25f * (gsum[i] + gl2[i]) + w[G_N + g] * gul[i];
}

// ---------------- predict MLP; iacc = 0.25*(giis+yi+im) inline ----------------
__global__ void k_pred(float* __restrict__ out, const int* __restrict__ gin,
                       const int* __restrict__ iin, const float* __restrict__ gf,
                       const float* __restrict__ t0, const float* __restrict__ t1,
                       const float* __restrict__ t2,
                       const float* __restrict__ pw1, const float* __restrict__ pb1,
                       const float* __restrict__ pw2, const float* __restrict__ pb2) {
    int wid = (blockIdx.x * blockDim.x + threadIdx.x) >> 5;
    int lane = threadIdx.x & 31;
    if (wid >= B_N) return;
    int g = __ldg(gin + wid), it = __ldg(iin + wid);
    size_t o = ((size_t)it << 5) + lane;
    float ia = 0.25f * (__ldg(t0 + o) + __ldg(t1 + o) + __ldg(t2 + o));
    float e = __ldg(gf + (size_t)g * 32 + lane) * ia;
    float s = 0.f;
    #pragma unroll
    for (int j = 0; j < 8; j++) {
        float p = e * __ldg(pw1 + lane * 8 + j);
        #pragma unroll
        for (int o2 = 16; o2 > 0; o2 >>= 1) p += __shfl_xor_sync(0xffffffffu, p, o2);
        s += fmaxf(p + pb1[j], 0.f) * pw2[j];
    }
    if (lane == 0) out[wid] = 1.f / (1.f + expf(-(s + pb2[0])));
}

// ---------------- host driver ----------------
static inline int cdiv(int a, int b) { return (a + b - 1) / b; }

extern "C" void kernel_launch(void* const* d_in, const int* in_sizes, int n_in,
                              void* d_out, int out_size) {
    const int*   gin  = (const int*)  d_in[0];
    const int*   iin  = (const int*)  d_in[1];
    const float* uemb = (const float*)d_in[2];
    const float* gemb = (const float*)d_in[3];
    const float* iemb = (const float*)d_in[4];
    const int*   ui_r = (const int*)  d_in[5];
    const int*   ui_c = (const int*)  d_in[6];
    const float* ui_v = (const float*)d_in[7];
    const int*   gi_r = (const int*)  d_in[8];
    const int*   gi_c = (const int*)  d_in[9];
    const float* gi_v = (const float*)d_in[10];
    const float* ovu  = (const float*)d_in[11];
    const float* ovi  = (const float*)d_in[12];
    const int*   agu  = (const int*)  d_in[13];
    const float* agm  = (const float*)d_in[14];
    const float* gw1  = (const float*)d_in[15];
    const float* gb1  = (const float*)d_in[16];
    const float* gw2  = (const float*)d_in[17];
    const float* gb2  = (const float*)d_in[18];
    const float* pw1  = (const float*)d_in[19];
    const float* pb1  = (const float*)d_in[20];
    const float* pw2  = (const float*)d_in[21];
    const float* pb2  = (const float*)d_in[22];
    float* out = (float*)d_out;
    const int nnz_ui = in_sizes[5];
    const int nnz_gi = in_sizes[8];

    float* S = nullptr;
    cudaGetSymbolAddress((void**)&S, d_scratch);

    const int TPB = 256;
    int spmm_ui_grid = cdiv(nnz_ui * 8, TPB);
    int spmm_gi_grid = cdiv(nnz_gi * 8, TPB);

    // single zero of all accumulation buffers (contiguous region)
    k_zero4<<<cdiv(984000,TPB),TPB>>>((float4*)S, 984000);

    // ======== UI graph conv: l1 -> UI_B, l2 -> UI_A, l3 -> UI_C ========
    k_spmm<<<spmm_ui_grid,TPB>>>(ui_r, ui_c, ui_v, nnz_ui, uemb, iemb, U_N,
                                 S + OFF_UI_B, U_N + I_N);
    k_spmm<<<spmm_ui_grid,TPB>>>(ui_r, ui_c, ui_v, nnz_ui,
                                 S + OFF_UI_B, S + OFF_UI_B + U_N*32, U_N,
                                 S + OFF_UI_A, U_N + I_N);
    k_spmm<<<spmm_ui_grid,TPB>>>(ui_r, ui_c, ui_v, nnz_ui,
                                 S + OFF_UI_A, S + OFF_UI_A + U_N*32, U_N,
                                 S + OFF_UI_C, U_N + I_N);
    // USUM / IEU / GSUM-init in one pass
    k_comb_ui<<<cdiv(168000,TPB),TPB>>>(S, (const float4*)uemb,
                                        (const float4*)iemb, (const float4*)gemb);

    // ======== GI graph conv: l1 -> GI_B, l2 -> GI_A, l3 -> GI_C ========
    k_spmm<<<spmm_gi_grid,TPB>>>(gi_r, gi_c, gi_v, nnz_gi, gemb, S + OFF_IEU, G_N,
                                 S + OFF_GI_B, G_N + I_N);
    k_spmm<<<spmm_gi_grid,TPB>>>(gi_r, gi_c, gi_v, nnz_gi,
                                 S + OFF_GI_B, S + OFF_GI_B + G_N*32, G_N,
                                 S + OFF_GI_A, G_N + I_N);
    k_spmm<<<spmm_gi_grid,TPB>>>(gi_r, gi_c, gi_v, nnz_gi,
                                 S + OFF_GI_A, S + OFF_GI_A + G_N*32, G_N,
                                 S + OFF_GI_C, G_N + I_N);
    // odd g_layers red straight into GSUM (rows < G only)
    k_spmm<<<spmm_gi_grid,TPB>>>(gi_r, gi_c, gi_v, nnz_gi, gemb, iemb, G_N,
                                 S + OFF_GSUM, G_N);
    k_spmm<<<spmm_gi_grid,TPB>>>(gi_r, gi_c, gi_v, nnz_gi, gemb, S + OFF_UI_A + U_N*32,
                                 G_N, S + OFF_GSUM, G_N);
    // GIIS = IEU + item parts of l1,l2,l3
    k_comb_gi<<<cdiv(64000,TPB),TPB>>>(S);

    // ======== social power series: fused user+item MM per hop ========
    int gxU = cdiv(U_N, 128), gxI = cdiv(I_N, 128);
    dim3 gmm(gxU + gxI, 8);
    // hop 1: YS = ovu@USUM ; YI = ovi@GIIS
    k_mm_tc2<<<gmm,256>>>(ovu, S + OFF_USUM, S + OFF_YS, U_N, gxU,
                          ovi, S + OFF_GIIS, S + OFF_YI, I_N);
    // hop 2: UM = ovu@YS ; IM = ovi@YI
    k_mm_tc2<<<gmm,256>>>(ovu, S + OFF_YS, S + OFF_UM, U_N, gxU,
                          ovi, S + OFF_YI, S + OFF_IM, I_N);

    // ======== pooling, gate, predict ========
    k_gul<<<cdiv(G_N*32, TPB), TPB>>>(S + OFF_GUL, agu, agm,
                                      S + OFF_USUM, S + OFF_YS, S + OFF_UM);
    k_gate<<<cdiv(2*G_N*32, TPB), TPB>>>(S + OFF_W, S + OFF_GSUM, S + OFF_GI_A,
                                         S + OFF_GUL, gw1, gb1, gw2, gb2);
    k_combine<<<cdiv(G_N*32, TPB), TPB>>>(S + OFF_GF, S + OFF_W, S + OFF_GSUM,
                                          S + OFF_GI_A, S + OFF_GUL);
    k_pred<<<cdiv(B_N*32, TPB), TPB>>>(out, gin, iin, S + OFF_GF,
                                       S + OFF_GIIS, S + OFF_YI, S + OFF_IM,
                                       pw1, pb1, pw2, pb2);
}

// round 10
// speedup vs baseline: 1.1451x; 1.1451x over previous
#include <cuda_runtime.h>
#include <cuda_bf16.h>
#include <cstdint>
#include <math.h>

// ---------------- problem constants ----------------
#define U_N   10000
#define G_N   3000
#define I_N   8000
#define B_N   4096
#define LM    20

// ---------------- scratch layout (floats) ----------------
// Zero-init region [0, 3936000) is one contiguous block -> single zero kernel.
constexpr int OFF_UI_A = 0;        // 576000  UI layer2 (l2) output
constexpr int OFF_UI_B = 576000;   // 576000  UI layer1 (l1) output
constexpr int OFF_UI_C = 1152000;  // 576000  UI layer3 (l3) output
constexpr int OFF_GI_A = 1728000;  // 352000  GI l2
constexpr int OFF_GI_B = 2080000;  // 352000  GI l1
constexpr int OFF_GI_C = 2432000;  // 352000  GI l3
constexpr int OFF_YS   = 2784000;  // 320000  user social term 1
constexpr int OFF_UM   = 3104000;  // 320000  user social term 2
constexpr int OFF_YI   = 3424000;  // 256000  item social term 1
constexpr int OFF_IM   = 3680000;  // 256000  item social term 2
// end of zeroed region (3936000)
constexpr int OFF_USUM = 3936000;  // 320000  sum of 4 UI user layers (unscaled)
constexpr int OFF_IEU  = 4256000;  // 256000  item_emb_for_user (0.25 * item sum)
constexpr int OFF_GIIS = 4512000;  // 256000  sum of 4 GI item layers (unscaled)
constexpr int OFF_GSUM = 4768000;  // 96000   gemb + odd g_layers (l2 part added in gate)
constexpr int OFF_GUL  = 4864000;  // 96000
constexpr int OFF_W    = 4960000;  // 6400
constexpr int OFF_GF   = 4966400;  // 96000
constexpr int SCRATCH_TOTAL = 5062400;

__device__ float d_scratch[SCRATCH_TOTAL];

// ---------------- elementwise helpers ----------------
__global__ void k_zero4(float4* p, int n4) {
    int i = blockIdx.x * blockDim.x + threadIdx.x;
    if (i < n4) p[i] = make_float4(0.f, 0.f, 0.f, 0.f);
}

__device__ __forceinline__ float4 add4(float4 a, float4 b) {
    return make_float4(a.x+b.x, a.y+b.y, a.z+b.z, a.w+b.w);
}
__device__ __forceinline__ float4 mul4(float4 a, float s) {
    return make_float4(a.x*s, a.y*s, a.z*s, a.w*s);
}

// Combine UI layers: USUM (user rows, unscaled sum incl. emb), IEU = 0.25*item sum.
// Tail segment initializes GSUM = gemb.
__global__ void k_comb_ui(float* __restrict__ S, const float4* __restrict__ uemb,
                          const float4* __restrict__ iemb, const float4* __restrict__ gemb) {
    int i = blockIdx.x * blockDim.x + threadIdx.x;
    const float4* A = (const float4*)(S + OFF_UI_A);
    const float4* B = (const float4*)(S + OFF_UI_B);
    const float4* C = (const float4*)(S + OFF_UI_C);
    if (i < 80000) {
        float4 s = add4(add4(uemb[i], B[i]), add4(A[i], C[i]));
        ((float4*)(S + OFF_USUM))[i] = s;
    } else if (i < 144000) {
        int j = i - 80000;
        float4 s = add4(add4(iemb[j], B[i]), add4(A[i], C[i]));
        ((float4*)(S + OFF_IEU))[j] = mul4(s, 0.25f);
    } else if (i < 168000) {
        int j = i - 144000;
        ((float4*)(S + OFF_GSUM))[j] = gemb[j];
    }
}

// Combine GI item layers: GIIS = IEU + item parts of l1,l2,l3 (unscaled).
__global__ void k_comb_gi(float* __restrict__ S) {
    int i = blockIdx.x * blockDim.x + threadIdx.x;
    if (i >= 64000) return;
    int j = G_N * 8 + i;  // item rows start at G_N*32 floats = G_N*8 float4s
    const float4* A = (const float4*)(S + OFF_GI_A);
    const float4* B = (const float4*)(S + OFF_GI_B);
    const float4* C = (const float4*)(S + OFF_GI_C);
    const float4* E = (const float4*)(S + OFF_IEU);
    ((float4*)(S + OFF_GIIS))[i] = add4(add4(E[i], B[j]), add4(A[j], C[j]));
}

// ---------------- COO SpMM, warp-cooperative index loads ----------------
__global__ void k_spmm(const int* __restrict__ rows, const int* __restrict__ cols,
                       const float* __restrict__ vals, int nnz,
                       const float* __restrict__ x0, const float* __restrict__ x1,
                       int split, float* __restrict__ out, int row_limit) {
    int gw = (blockIdx.x * blockDim.x + threadIdx.x) >> 5;
    int lane = threadIdx.x & 31;
    int e0 = gw << 2;
    if (e0 >= nnz) return;
    int ld = 0;
    int which = lane >> 2;              // 0:rows 1:cols 2:vals
    int j4 = e0 + (lane & 3);
    if (j4 < nnz) {
        if (which == 0)      ld = __ldg(rows + j4);
        else if (which == 1) ld = __ldg(cols + j4);
        else if (which == 2) ld = __float_as_int(__ldg(vals + j4));
    }
    int sub = lane >> 3;                // which of the 4 edges
    int l4  = (lane & 7) << 2;          // float4 slot within row
    int e = e0 + sub;
    int r =                 __shfl_sync(0xffffffffu, ld, sub);
    int c =                 __shfl_sync(0xffffffffu, ld, 4 + sub);
    float v = __int_as_float(__shfl_sync(0xffffffffu, ld, 8 + sub));
    if (e >= nnz || r >= row_limit) return;
    const float* src = (c < split) ? (x0 + ((size_t)c << 5))
                                   : (x1 + ((size_t)(c - split) << 5));
    float4 xv = *(const float4*)(src + l4);
    asm volatile("red.global.add.v4.f32 [%0], {%1, %2, %3, %4};"
                 :: "l"(out + ((size_t)r << 5) + l4),
                    "f"(v*xv.x), "f"(v*xv.y), "f"(v*xv.z), "f"(v*xv.w) : "memory");
}

// ---------------- tensor-core dense MM: y += A@x (split-bf16 3-term) ----------------
#define MMKC 32
#define MALD 40

__device__ __forceinline__ uint32_t cvta_s(const void* p) {
    return (uint32_t)__cvta_generic_to_shared(p);
}
__device__ __forceinline__ void ldm_x4(uint32_t* r, uint32_t addr) {
    asm volatile("ldmatrix.sync.aligned.m8n8.x4.shared.b16 {%0,%1,%2,%3}, [%4];"
                 : "=r"(r[0]), "=r"(r[1]), "=r"(r[2]), "=r"(r[3]) : "r"(addr));
}
__device__ __forceinline__ void ldm_x4_t(uint32_t* r, uint32_t addr) {
    asm volatile("ldmatrix.sync.aligned.m8n8.x4.trans.shared.b16 {%0,%1,%2,%3}, [%4];"
                 : "=r"(r[0]), "=r"(r[1]), "=r"(r[2]), "=r"(r[3]) : "r"(addr));
}
__device__ __forceinline__ void mma_bf16(float* d, const uint32_t* a,
                                         uint32_t b0, uint32_t b1) {
    asm volatile("mma.sync.aligned.m16n8k16.row.col.f32.bf16.bf16.f32 "
                 "{%0,%1,%2,%3}, {%4,%5,%6,%7}, {%8,%9}, {%0,%1,%2,%3};"
                 : "+f"(d[0]), "+f"(d[1]), "+f"(d[2]), "+f"(d[3])
                 : "r"(a[0]), "r"(a[1]), "r"(a[2]), "r"(a[3]), "r"(b0), "r"(b1));
}
__device__ __forceinline__ void red2(float* p, float a, float b) {
    asm volatile("red.global.add.v2.f32 [%0], {%1, %2};"
                 :: "l"(p), "f"(a), "f"(b) : "memory");
}
__device__ __forceinline__ void st_split4(float4 v, __nv_bfloat16* hd, __nv_bfloat16* ldst) {
    uint32_t x0 = __float_as_uint(v.x), x1 = __float_as_uint(v.y);
    uint32_t x2 = __float_as_uint(v.z), x3 = __float_as_uint(v.w);
    uint32_t h01, h23;
    asm("prmt.b32 %0, %1, %2, 0x7632;" : "=r"(h01) : "r"(x0), "r"(x1));
    asm("prmt.b32 %0, %1, %2, 0x7632;" : "=r"(h23) : "r"(x2), "r"(x3));
    float l0 = v.x - __uint_as_float(x0 & 0xFFFF0000u);
    float l1 = v.y - __uint_as_float(x1 & 0xFFFF0000u);
    float l2 = v.z - __uint_as_float(x2 & 0xFFFF0000u);
    float l3 = v.w - __uint_as_float(x3 & 0xFFFF0000u);
    uint32_t lo01, lo23;
    asm("prmt.b32 %0, %1, %2, 0x7632;" : "=r"(lo01)
        : "r"(__float_as_uint(l0)), "r"(__float_as_uint(l1)));
    asm("prmt.b32 %0, %1, %2, 0x7632;" : "=r"(lo23)
        : "r"(__float_as_uint(l2)), "r"(__float_as_uint(l3)));
    *(uint2*)hd   = make_uint2(h01, h23);
    *(uint2*)ldst = make_uint2(lo01, lo23);
}

__global__ void __launch_bounds__(256, 3)
k_mm_tc(const float* __restrict__ A, const float* __restrict__ x,
        float* __restrict__ y, int n) {
    __shared__ __nv_bfloat16 Ah[128 * MALD], Al[128 * MALD];
    __shared__ __nv_bfloat16 Xh[MMKC * MALD], Xl[MMKC * MALD];
    int tid = threadIdx.x;
    int warp = tid >> 5, lane = tid & 31;
    int m0 = blockIdx.x * 128;

    int nchunks = (n + MMKC - 1) / MMKC;
    int per = (nchunks + gridDim.y - 1) / gridDim.y;
    int ci0 = blockIdx.y * per;
    int ci1 = min(nchunks, ci0 + per);

    float acc[4][4];
    #pragma unroll
    for (int f = 0; f < 4; f++)
        #pragma unroll
        for (int j = 0; j < 4; j++) acc[f][j] = 0.f;

    uint32_t aAddrH = cvta_s(&Ah[(warp * 16 + (lane & 15)) * MALD + ((lane >> 4) << 3)]);
    uint32_t aAddrL = cvta_s(&Al[(warp * 16 + (lane & 15)) * MALD + ((lane >> 4) << 3)]);
    uint32_t xBaseH = cvta_s(&Xh[(lane & 15) * MALD + ((lane >> 4) << 3)]);
    uint32_t xBaseL = cvta_s(&Xl[(lane & 15) * MALD + ((lane >> 4) << 3)]);

    int ar = tid >> 1, ahalf = tid & 1;
    int xr = tid >> 3, xc = (tid & 7) << 2;
    int gr = m0 + ar;
    const float* Arow = A + (size_t)gr * n + ahalf * 16;

    float4 aR[4], xR;
    const float4 Z4 = make_float4(0.f, 0.f, 0.f, 0.f);
    {
        int k0 = ci0 * MMKC;
        xR = Z4;
        if (k0 + xr < n) xR = *(const float4*)(x + (size_t)(k0 + xr) * 32 + xc);
        #pragma unroll
        for (int j = 0; j < 4; j++) {
            int col = ahalf * 16 + j * 4;
            aR[j] = Z4;
            if (gr < n && (k0 + col + 4) <= n) aR[j] = *(const float4*)(Arow + k0 + j * 4);
        }
    }

    for (int ci = ci0; ci < ci1; ci++) {
        st_split4(xR, &Xh[xr * MALD + xc], &Xl[xr * MALD + xc]);
        #pragma unroll
        for (int j = 0; j < 4; j++) {
            int col = ahalf * 16 + j * 4;
            st_split4(aR[j], &Ah[ar * MALD + col], &Al[ar * MALD + col]);
        }
        __syncthreads();
        if (ci + 1 < ci1) {
            int k0 = (ci + 1) * MMKC;
            xR = Z4;
            if (k0 + xr < n) xR = *(const float4*)(x + (size_t)(k0 + xr) * 32 + xc);
            #pragma unroll
            for (int j = 0; j < 4; j++) {
                int col = ahalf * 16 + j * 4;
                aR[j] = Z4;
                if (gr < n && (k0 + col + 4) <= n) aR[j] = *(const float4*)(Arow + k0 + j * 4);
            }
        }
        #pragma unroll
        for (int ks = 0; ks < MMKC; ks += 16) {
            uint32_t afh[4], afl[4];
            ldm_x4(afh, aAddrH + ks * 2);
            ldm_x4(afl, aAddrL + ks * 2);
            #pragma unroll
            for (int np = 0; np < 2; np++) {
                uint32_t bh[4], bl[4];
                uint32_t off = (uint32_t)(ks * MALD + np * 16) * 2;
                ldm_x4_t(bh, xBaseH + off);
                ldm_x4_t(bl, xBaseL + off);
                mma_bf16(acc[np * 2 + 0], afh, bh[0], bh[1]);
                mma_bf16(acc[np * 2 + 1], afh, bh[2], bh[3]);
                mma_bf16(acc[np * 2 + 0], afh, bl[0], bl[1]);
                mma_bf16(acc[np * 2 + 1], afh, bl[2], bl[3]);
                mma_bf16(acc[np * 2 + 0], afl, bh[0], bh[1]);
                mma_bf16(acc[np * 2 + 1], afl, bh[2], bh[3]);
            }
        }
        __syncthreads();
    }

    int gr8 = lane >> 2, cc = (lane & 3) * 2;
    #pragma unroll
    for (int f = 0; f < 4; f++) {
        int nc = f * 8 + cc;
        int r0 = m0 + warp * 16 + gr8;
        int r1 = r0 + 8;
        if (r0 < n) red2(y + (size_t)r0 * 32 + nc, acc[f][0], acc[f][1]);
        if (r1 < n) red2(y + (size_t)r1 * 32 + nc, acc[f][2], acc[f][3]);
    }
}

// ---------------- group_userlayer: pool over 0.25*(usum+ys+um) ----------------
__global__ void k_gul(float* __restrict__ gul, const int* __restrict__ users,
                      const float* __restrict__ mask, const float* __restrict__ t0,
                      const float* __restrict__ t1, const float* __restrict__ t2) {
    int i = blockIdx.x * blockDim.x + threadIdx.x;
    if (i >= G_N * 32) return;
    int g = i >> 5, d = i & 31;
    float s = 0.f;
    #pragma unroll
    for (int l = 0; l < LM; l++) {
        int u = __ldg(users + g * LM + l);
        size_t o = ((size_t)u << 5) + d;
        float acc = __ldg(t0 + o) + __ldg(t1 + o) + __ldg(t2 + o);
        s = fmaf(__ldg(mask + g * LM + l), acc, s);
    }
    gul[i] = 0.25f * s;
}

// ---------------- gate MLP; g_emb = 0.25*(gsum+gl2) inline ----------------
__global__ void k_gate(float* __restrict__ w, const float* __restrict__ gsum,
                       const float* __restrict__ gl2, const float* __restrict__ gul,
                       const float* __restrict__ w1, const float* __restrict__ b1,
                       const float* __restrict__ w2, const float* __restrict__ b2) {
    int wid = (blockIdx.x * blockDim.x + threadIdx.x) >> 5;
    int lane = threadIdx.x & 31;
    if (wid >= 2 * G_N) return;
    float xd;
    if (wid < G_N) {
        size_t o = (size_t)wid * 32 + lane;
        xd = 0.25f * (__ldg(gsum + o) + __ldg(gl2 + o));
    } else {
        xd = __ldg(gul + (size_t)(wid - G_N) * 32 + lane);
    }
    float h = b1[lane];
    #pragma unroll
    for (int d = 0; d < 32; d++) {
        float a = __shfl_sync(0xffffffffu, xd, d);
        h = fmaf(a, __ldg(w1 + d * 32 + lane), h);
    }
    h = fmaxf(h, 0.f);
    float t = h * __ldg(w2 + lane);
    #pragma unroll
    for (int o = 16; o > 0; o >>= 1) t += __shfl_xor_sync(0xffffffffu, t, o);
    if (lane == 0) w[wid] = 1.f / (1.f + expf(-(t + b2[0])));
}

__global__ void k_combine(float* __restrict__ gf, const float* __restrict__ w,
                          const float* __restrict__ gsum, const float* __restrict__ gl2,
                          const float* __restrict__ gul) {
    int i = blockIdx.x * blockDim.x + threadIdx.x;
    if (i >= G_N * 32) return;
    int g = i >> 5;
    gf[i] = w[g] * 0.25f * (gsum[i] + gl2[i]) + w[G_N + g] * gul[i];
}

// ---------------- predict MLP; iacc = 0.25*(giis+yi+im) inline ----------------
__global__ void k_pred(float* __restrict__ out, const int* __restrict__ gin,
                       const int* __restrict__ iin, const float* __restrict__ gf,
                       const float* __restrict__ t0, const float* __restrict__ t1,
                       const float* __restrict__ t2,
                       const float* __restrict__ pw1, const float* __restrict__ pb1,
                       const float* __restrict__ pw2, const float* __restrict__ pb2) {
    int wid = (blockIdx.x * blockDim.x + threadIdx.x) >> 5;
    int lane = threadIdx.x & 31;
    if (wid >= B_N) return;
    int g = __ldg(gin + wid), it = __ldg(iin + wid);
    size_t o = ((size_t)it << 5) + lane;
    float ia = 0.25f * (__ldg(t0 + o) + __ldg(t1 + o) + __ldg(t2 + o));
    float e = __ldg(gf + (size_t)g * 32 + lane) * ia;
    float s = 0.f;
    #pragma unroll
    for (int j = 0; j < 8; j++) {
        float p = e * __ldg(pw1 + lane * 8 + j);
        #pragma unroll
        for (int o2 = 16; o2 > 0; o2 >>= 1) p += __shfl_xor_sync(0xffffffffu, p, o2);
        s += fmaxf(p + pb1[j], 0.f) * pw2[j];
    }
    if (lane == 0) out[wid] = 1.f / (1.f + expf(-(s + pb2[0])));
}

// ---------------- host driver ----------------
static inline int cdiv(int a, int b) { return (a + b - 1) / b; }

extern "C" void kernel_launch(void* const* d_in, const int* in_sizes, int n_in,
                              void* d_out, int out_size) {
    const int*   gin  = (const int*)  d_in[0];
    const int*   iin  = (const int*)  d_in[1];
    const float* uemb = (const float*)d_in[2];
    const float* gemb = (const float*)d_in[3];
    const float* iemb = (const float*)d_in[4];
    const int*   ui_r = (const int*)  d_in[5];
    const int*   ui_c = (const int*)  d_in[6];
    const float* ui_v = (const float*)d_in[7];
    const int*   gi_r = (const int*)  d_in[8];
    const int*   gi_c = (const int*)  d_in[9];
    const float* gi_v = (const float*)d_in[10];
    const float* ovu  = (const float*)d_in[11];
    const float* ovi  = (const float*)d_in[12];
    const int*   agu  = (const int*)  d_in[13];
    const float* agm  = (const float*)d_in[14];
    const float* gw1  = (const float*)d_in[15];
    const float* gb1  = (const float*)d_in[16];
    const float* gw2  = (const float*)d_in[17];
    const float* gb2  = (const float*)d_in[18];
    const float* pw1  = (const float*)d_in[19];
    const float* pb1  = (const float*)d_in[20];
    const float* pw2  = (const float*)d_in[21];
    const float* pb2  = (const float*)d_in[22];
    float* out = (float*)d_out;
    const int nnz_ui = in_sizes[5];
    const int nnz_gi = in_sizes[8];

    float* S = nullptr;
    cudaGetSymbolAddress((void**)&S, d_scratch);

    const int TPB = 256;
    int spmm_ui_grid = cdiv(nnz_ui * 8, TPB);
    int spmm_gi_grid = cdiv(nnz_gi * 8, TPB);

    // fork/join machinery (created+destroyed each call; deterministic)
    cudaStream_t s2;
    cudaStreamCreateWithFlags(&s2, cudaStreamNonBlocking);
    cudaEvent_t evFork, evJoin;
    cudaEventCreateWithFlags(&evFork, cudaEventDisableTiming);
    cudaEventCreateWithFlags(&evJoin, cudaEventDisableTiming);

    // single zero of all accumulation buffers (contiguous region)
    k_zero4<<<cdiv(984000,TPB),TPB>>>((float4*)S, 984000);

    // ======== UI graph conv: l1 -> UI_B, l2 -> UI_A, l3 -> UI_C ========
    k_spmm<<<spmm_ui_grid,TPB>>>(ui_r, ui_c, ui_v, nnz_ui, uemb, iemb, U_N,
                                 S + OFF_UI_B, U_N + I_N);
    k_spmm<<<spmm_ui_grid,TPB>>>(ui_r, ui_c, ui_v, nnz_ui,
                                 S + OFF_UI_B, S + OFF_UI_B + U_N*32, U_N,
                                 S + OFF_UI_A, U_N + I_N);
    k_spmm<<<spmm_ui_grid,TPB>>>(ui_r, ui_c, ui_v, nnz_ui,
                                 S + OFF_UI_A, S + OFF_UI_A + U_N*32, U_N,
                                 S + OFF_UI_C, U_N + I_N);
    // USUM / IEU / GSUM-init in one pass
    k_comb_ui<<<cdiv(168000,TPB),TPB>>>(S, (const float4*)uemb,
                                        (const float4*)iemb, (const float4*)gemb);

    // ---- fork: user social MM chain runs on s2, overlapping GI chain ----
    cudaEventRecord(evFork, 0);
    cudaStreamWaitEvent(s2, evFork, 0);
    {
        dim3 g(cdiv(U_N, 128), 8);
        k_mm_tc<<<g, 256, 0, s2>>>(ovu, S + OFF_USUM, S + OFF_YS, U_N);
        k_mm_tc<<<g, 256, 0, s2>>>(ovu, S + OFF_YS,   S + OFF_UM, U_N);
    }

    // ======== GI graph conv on stream 0: l1 -> GI_B, l2 -> GI_A, l3 -> GI_C ========
    k_spmm<<<spmm_gi_grid,TPB>>>(gi_r, gi_c, gi_v, nnz_gi, gemb, S + OFF_IEU, G_N,
                                 S + OFF_GI_B, G_N + I_N);
    k_spmm<<<spmm_gi_grid,TPB>>>(gi_r, gi_c, gi_v, nnz_gi,
                                 S + OFF_GI_B, S + OFF_GI_B + G_N*32, G_N,
                                 S + OFF_GI_A, G_N + I_N);
    k_spmm<<<spmm_gi_grid,TPB>>>(gi_r, gi_c, gi_v, nnz_gi,
                                 S + OFF_GI_A, S + OFF_GI_A + G_N*32, G_N,
                                 S + OFF_GI_C, G_N + I_N);
    // odd g_layers red straight into GSUM (rows < G only)
    k_spmm<<<spmm_gi_grid,TPB>>>(gi_r, gi_c, gi_v, nnz_gi, gemb, iemb, G_N,
                                 S + OFF_GSUM, G_N);
    k_spmm<<<spmm_gi_grid,TPB>>>(gi_r, gi_c, gi_v, nnz_gi, gemb, S + OFF_UI_A + U_N*32,
                                 G_N, S + OFF_GSUM, G_N);
    // GIIS = IEU + item parts of l1,l2,l3
    k_comb_gi<<<cdiv(64000,TPB),TPB>>>(S);

    // ======== item social MM chain on stream 0 ========
    {
        dim3 g(cdiv(I_N, 128), 8);
        k_mm_tc<<<g, 256>>>(ovi, S + OFF_GIIS, S + OFF_YI, I_N);
        k_mm_tc<<<g, 256>>>(ovi, S + OFF_YI,   S + OFF_IM, I_N);
    }

    // ---- join: user-MM branch must finish before pooling ----
    cudaEventRecord(evJoin, s2);
    cudaStreamWaitEvent(0, evJoin, 0);

    // ======== pooling, gate, predict ========
    k_gul<<<cdiv(G_N*32, TPB), TPB>>>(S + OFF_GUL, agu, agm,
                                      S + OFF_USUM, S + OFF_YS, S + OFF_UM);
    k_gate<<<cdiv(2*G_N*32, TPB), TPB>>>(S + OFF_W, S + OFF_GSUM, S + OFF_GI_A,
                                         S + OFF_GUL, gw1, gb1, gw2, gb2);
    k_combine<<<cdiv(G_N*32, TPB), TPB>>>(S + OFF_GF, S + OFF_W, S + OFF_GSUM,
                                          S + OFF_GI_A, S + OFF_GUL);
    k_pred<<<cdiv(B_N*32, TPB), TPB>>>(out, gin, iin, S + OFF_GF,
                                       S + OFF_GIIS, S + OFF_YI, S + OFF_IM,
                                       pw1, pb1, pw2, pb2);

    cudaEventDestroy(evFork);
    cudaEventDestroy(evJoin);
    cudaStreamDestroy(s2);
}

// round 13
// speedup vs baseline: 1.1932x; 1.0420x over previous
#include <cuda_runtime.h>
#include <cuda_bf16.h>
#include <cstdint>
#include <math.h>

// ---------------- problem constants ----------------
#define U_N   10000
#define G_N   3000
#define I_N   8000
#define B_N   4096
#define LM    20

// ---------------- scratch layout (floats) ----------------
constexpr int OFF_UI_A = 0;        // 576000  UI l2
constexpr int OFF_UI_B = 576000;   // 576000  UI l1
constexpr int OFF_UI_C = 1152000;  // 576000  UI l3
constexpr int OFF_GI_A = 1728000;  // 352000  GI l2
constexpr int OFF_GI_B = 2080000;  // 352000  GI l1
constexpr int OFF_GI_C = 2432000;  // 352000  GI l3
constexpr int OFF_YS   = 2784000;  // 320000  user social term 1
constexpr int OFF_UM   = 3104000;  // 320000  user social term 2
constexpr int OFF_YI   = 3424000;  // 256000  item social term 1
constexpr int OFF_IM   = 3680000;  // 256000  item social term 2
// end of zeroed region (3936000)
constexpr int OFF_USUM = 3936000;  // 320000
constexpr int OFF_IEU  = 4256000;  // 256000
constexpr int OFF_GIIS = 4512000;  // 256000
constexpr int OFF_GSUM = 4768000;  // 96000
constexpr int OFF_GUL  = 4864000;  // 96000
constexpr int OFF_W    = 4960000;  // 6400
constexpr int OFF_GF   = 4966400;  // 96000
constexpr int SCRATCH_TOTAL = 5062400;

__device__ float d_scratch[SCRATCH_TOTAL];

// ---------------- elementwise helpers ----------------
__global__ void k_zero4(float4* p, int n4) {
    int i = blockIdx.x * blockDim.x + threadIdx.x;
    if (i < n4) p[i] = make_float4(0.f, 0.f, 0.f, 0.f);
}

__device__ __forceinline__ float4 add4(float4 a, float4 b) {
    return make_float4(a.x+b.x, a.y+b.y, a.z+b.z, a.w+b.w);
}
__device__ __forceinline__ float4 mul4(float4 a, float s) {
    return make_float4(a.x*s, a.y*s, a.z*s, a.w*s);
}

__global__ void k_comb_ui(float* __restrict__ S, const float4* __restrict__ uemb,
                          const float4* __restrict__ iemb, const float4* __restrict__ gemb) {
    int i = blockIdx.x * blockDim.x + threadIdx.x;
    const float4* A = (const float4*)(S + OFF_UI_A);
    const float4* B = (const float4*)(S + OFF_UI_B);
    const float4* C = (const float4*)(S + OFF_UI_C);
    if (i < 80000) {
        float4 s = add4(add4(uemb[i], B[i]), add4(A[i], C[i]));
        ((float4*)(S + OFF_USUM))[i] = s;
    } else if (i < 144000) {
        int j = i - 80000;
        float4 s = add4(add4(iemb[j], B[i]), add4(A[i], C[i]));
        ((float4*)(S + OFF_IEU))[j] = mul4(s, 0.25f);
    } else if (i < 168000) {
        int j = i - 144000;
        ((float4*)(S + OFF_GSUM))[j] = gemb[j];
    }
}

__global__ void k_comb_gi(float* __restrict__ S) {
    int i = blockIdx.x * blockDim.x + threadIdx.x;
    if (i >= 64000) return;
    int j = G_N * 8 + i;
    const float4* A = (const float4*)(S + OFF_GI_A);
    const float4* B = (const float4*)(S + OFF_GI_B);
    const float4* C = (const float4*)(S + OFF_GI_C);
    const float4* E = (const float4*)(S + OFF_IEU);
    ((float4*)(S + OFF_GIIS))[i] = add4(add4(E[i], B[j]), add4(A[j], C[j]));
}

// ---------------- COO SpMM: 8 edges/warp, 2-way ILP per lane ----------------
// lanes 0-11 load fields of edges e0..e3, lanes 16-27 of e4..e7 (shfl broadcast).
// Each 8-lane group owns one edge from each half: two independent gather+red chains.
__device__ __forceinline__ void red4(float* p, float a, float b, float c, float d) {
    asm volatile("red.global.add.v4.f32 [%0], {%1, %2, %3, %4};"
                 :: "l"(p), "f"(a), "f"(b), "f"(c), "f"(d) : "memory");
}
__global__ void k_spmm(const int* __restrict__ rows, const int* __restrict__ cols,
                       const float* __restrict__ vals, int nnz,
                       const float* __restrict__ x0, const float* __restrict__ x1,
                       int split, float* __restrict__ out, int row_limit) {
    int gw = (blockIdx.x * blockDim.x + threadIdx.x) >> 5;
    int lane = threadIdx.x & 31;
    int e0 = gw << 3;
    if (e0 >= nnz) return;
    int ld = 0;
    int half = lane >> 4;           // 0: edges e0..3, 1: edges e4..7
    int hl = lane & 15;
    int which = hl >> 2;            // 0 rows, 1 cols, 2 vals, 3 idle
    int j4 = e0 + half * 4 + (hl & 3);
    if (which < 3 && j4 < nnz) {
        if (which == 0)      ld = __ldg(rows + j4);
        else if (which == 1) ld = __ldg(cols + j4);
        else                 ld = __float_as_int(__ldg(vals + j4));
    }
    int subw = lane >> 3;           // 0..3: edge index within quad
    int l4   = (lane & 7) << 2;     // float4 slot
    int rA =                 __shfl_sync(0xffffffffu, ld, subw);
    int cA =                 __shfl_sync(0xffffffffu, ld, 4 + subw);
    float vA = __int_as_float(__shfl_sync(0xffffffffu, ld, 8 + subw));
    int rB =                 __shfl_sync(0xffffffffu, ld, 16 + subw);
    int cB =                 __shfl_sync(0xffffffffu, ld, 20 + subw);
    float vB = __int_as_float(__shfl_sync(0xffffffffu, ld, 24 + subw));
    int eA = e0 + subw, eB = e0 + 4 + subw;
    bool doA = (eA < nnz) && (rA < row_limit);
    bool doB = (eB < nnz) && (rB < row_limit);
    float4 xa, xb;
    if (doA) {
        const float* s = (cA < split) ? x0 + ((size_t)cA << 5)
                                      : x1 + ((size_t)(cA - split) << 5);
        xa = *(const float4*)(s + l4);
    }
    if (doB) {
        const float* s = (cB < split) ? x0 + ((size_t)cB << 5)
                                      : x1 + ((size_t)(cB - split) << 5);
        xb = *(const float4*)(s + l4);
    }
    if (doA) red4(out + ((size_t)rA << 5) + l4, vA*xa.x, vA*xa.y, vA*xa.z, vA*xa.w);
    if (doB) red4(out + ((size_t)rB << 5) + l4, vB*xb.x, vB*xb.y, vB*xb.z, vB*xb.w);
}

// ---------------- tensor-core dense MM: y += A@x, double-buffered stages ----------------
#define MMKC 32
#define MALD 40
#define A_STAGE (128 * MALD)      // bf16 elems per A stage
#define X_STAGE (MMKC * MALD)

__device__ __forceinline__ uint32_t cvta_s(const void* p) {
    return (uint32_t)__cvta_generic_to_shared(p);
}
__device__ __forceinline__ void ldm_x4(uint32_t* r, uint32_t addr) {
    asm volatile("ldmatrix.sync.aligned.m8n8.x4.shared.b16 {%0,%1,%2,%3}, [%4];"
                 : "=r"(r[0]), "=r"(r[1]), "=r"(r[2]), "=r"(r[3]) : "r"(addr));
}
__device__ __forceinline__ void ldm_x4_t(uint32_t* r, uint32_t addr) {
    asm volatile("ldmatrix.sync.aligned.m8n8.x4.trans.shared.b16 {%0,%1,%2,%3}, [%4];"
                 : "=r"(r[0]), "=r"(r[1]), "=r"(r[2]), "=r"(r[3]) : "r"(addr));
}
__device__ __forceinline__ void mma_bf16(float* d, const uint32_t* a,
                                         uint32_t b0, uint32_t b1) {
    asm volatile("mma.sync.aligned.m16n8k16.row.col.f32.bf16.bf16.f32 "
                 "{%0,%1,%2,%3}, {%4,%5,%6,%7}, {%8,%9}, {%0,%1,%2,%3};"
                 : "+f"(d[0]), "+f"(d[1]), "+f"(d[2]), "+f"(d[3])
                 : "r"(a[0]), "r"(a[1]), "r"(a[2]), "r"(a[3]), "r"(b0), "r"(b1));
}
__device__ __forceinline__ void red2(float* p, float a, float b) {
    asm volatile("red.global.add.v2.f32 [%0], {%1, %2};"
                 :: "l"(p), "f"(a), "f"(b) : "memory");
}
__device__ __forceinline__ void st_split4(float4 v, __nv_bfloat16* hd, __nv_bfloat16* ldst) {
    uint32_t x0 = __float_as_uint(v.x), x1 = __float_as_uint(v.y);
    uint32_t x2 = __float_as_uint(v.z), x3 = __float_as_uint(v.w);
    uint32_t h01, h23;
    asm("prmt.b32 %0, %1, %2, 0x7632;" : "=r"(h01) : "r"(x0), "r"(x1));
    asm("prmt.b32 %0, %1, %2, 0x7632;" : "=r"(h23) : "r"(x2), "r"(x3));
    float l0 = v.x - __uint_as_float(x0 & 0xFFFF0000u);
    float l1 = v.y - __uint_as_float(x1 & 0xFFFF0000u);
    float l2 = v.z - __uint_as_float(x2 & 0xFFFF0000u);
    float l3 = v.w - __uint_as_float(x3 & 0xFFFF0000u);
    uint32_t lo01, lo23;
    asm("prmt.b32 %0, %1, %2, 0x7632;" : "=r"(lo01)
        : "r"(__float_as_uint(l0)), "r"(__float_as_uint(l1)));
    asm("prmt.b32 %0, %1, %2, 0x7632;" : "=r"(lo23)
        : "r"(__float_as_uint(l2)), "r"(__float_as_uint(l3)));
    *(uint2*)hd   = make_uint2(h01, h23);
    *(uint2*)ldst = make_uint2(lo01, lo23);
}

__global__ void __launch_bounds__(256, 3)
k_mm_tc(const float* __restrict__ A, const float* __restrict__ x,
        float* __restrict__ y, int n) {
    __shared__ __nv_bfloat16 Ah[2][A_STAGE], Al[2][A_STAGE];
    __shared__ __nv_bfloat16 Xh[2][X_STAGE], Xl[2][X_STAGE];
    int tid = threadIdx.x;
    int warp = tid >> 5, lane = tid & 31;
    int m0 = blockIdx.x * 128;

    int nchunks = (n + MMKC - 1) / MMKC;
    int per = (nchunks + gridDim.y - 1) / gridDim.y;
    int ci0 = blockIdx.y * per;
    int ci1 = min(nchunks, ci0 + per);

    float acc[4][4];
    #pragma unroll
    for (int f = 0; f < 4; f++)
        #pragma unroll
        for (int j = 0; j < 4; j++) acc[f][j] = 0.f;

    uint32_t aAddrH0 = cvta_s(&Ah[0][(warp * 16 + (lane & 15)) * MALD + ((lane >> 4) << 3)]);
    uint32_t aAddrL0 = cvta_s(&Al[0][(warp * 16 + (lane & 15)) * MALD + ((lane >> 4) << 3)]);
    uint32_t xBaseH0 = cvta_s(&Xh[0][(lane & 15) * MALD + ((lane >> 4) << 3)]);
    uint32_t xBaseL0 = cvta_s(&Xl[0][(lane & 15) * MALD + ((lane >> 4) << 3)]);

    int ar = tid >> 1, ahalf = tid & 1;
    int xr = tid >> 3, xc = (tid & 7) << 2;
    int gr = m0 + ar;
    const float* Arow = A + (size_t)gr * n + ahalf * 16;

    float4 aR[4], xR;
    const float4 Z4 = make_float4(0.f, 0.f, 0.f, 0.f);
    {
        int k0 = ci0 * MMKC;
        xR = Z4;
        if (k0 + xr < n) xR = *(const float4*)(x + (size_t)(k0 + xr) * 32 + xc);
        #pragma unroll
        for (int j = 0; j < 4; j++) {
            int col = ahalf * 16 + j * 4;
            aR[j] = Z4;
            if (gr < n && (k0 + col + 4) <= n) aR[j] = *(const float4*)(Arow + k0 + j * 4);
        }
    }

    for (int ci = ci0; ci < ci1; ci++) {
        int s = ci & 1;
        // convert current registers into stage s
        st_split4(xR, &Xh[s][xr * MALD + xc], &Xl[s][xr * MALD + xc]);
        #pragma unroll
        for (int j = 0; j < 4; j++) {
            int col = ahalf * 16 + j * 4;
            st_split4(aR[j], &Ah[s][ar * MALD + col], &Al[s][ar * MALD + col]);
        }
        __syncthreads();   // convert(s) complete across warps; prior mma used stage 1-s
        // prefetch next chunk (latency hidden under MMA)
        if (ci + 1 < ci1) {
            int k0 = (ci + 1) * MMKC;
            xR = Z4;
            if (k0 + xr < n) xR = *(const float4*)(x + (size_t)(k0 + xr) * 32 + xc);
            #pragma unroll
            for (int j = 0; j < 4; j++) {
                int col = ahalf * 16 + j * 4;
                aR[j] = Z4;
                if (gr < n && (k0 + col + 4) <= n) aR[j] = *(const float4*)(Arow + k0 + j * 4);
            }
        }
        // MMA on stage s (no trailing barrier: next convert targets stage 1-s)
        uint32_t aOff = (uint32_t)s * (A_STAGE * 2);
        uint32_t xOff = (uint32_t)s * (X_STAGE * 2);
        #pragma unroll
        for (int ks = 0; ks < MMKC; ks += 16) {
            uint32_t afh[4], afl[4];
            ldm_x4(afh, aAddrH0 + aOff + ks * 2);
            ldm_x4(afl, aAddrL0 + aOff + ks * 2);
            #pragma unroll
            for (int np = 0; np < 2; np++) {
                uint32_t bh[4], bl[4];
                uint32_t off = (uint32_t)(ks * MALD + np * 16) * 2;
                ldm_x4_t(bh, xBaseH0 + xOff + off);
                ldm_x4_t(bl, xBaseL0 + xOff + off);
                mma_bf16(acc[np * 2 + 0], afh, bh[0], bh[1]);
                mma_bf16(acc[np * 2 + 1], afh, bh[2], bh[3]);
                mma_bf16(acc[np * 2 + 0], afh, bl[0], bl[1]);
                mma_bf16(acc[np * 2 + 1], afh, bl[2], bl[3]);
                mma_bf16(acc[np * 2 + 0], afl, bh[0], bh[1]);
                mma_bf16(acc[np * 2 + 1], afl, bh[2], bh[3]);
            }
        }
    }

    int gr8 = lane >> 2, cc = (lane & 3) * 2;
    #pragma unroll
    for (int f = 0; f < 4; f++) {
        int nc = f * 8 + cc;
        int r0 = m0 + warp * 16 + gr8;
        int r1 = r0 + 8;
        if (r0 < n) red2(y + (size_t)r0 * 32 + nc, acc[f][0], acc[f][1]);
        if (r1 < n) red2(y + (size_t)r1 * 32 + nc, acc[f][2], acc[f][3]);
    }
}

// ---------------- group_userlayer: pool over 0.25*(usum+ys+um) ----------------
__global__ void k_gul(float* __restrict__ gul, const int* __restrict__ users,
                      const float* __restrict__ mask, const float* __restrict__ t0,
                      const float* __restrict__ t1, const float* __restrict__ t2) {
    int i = blockIdx.x * blockDim.x + threadIdx.x;
    if (i >= G_N * 32) return;
    int g = i >> 5, d = i & 31;
    float s = 0.f;
    #pragma unroll
    for (int l = 0; l < LM; l++) {
        int u = __ldg(users + g * LM + l);
        size_t o = ((size_t)u << 5) + d;
        float acc = __ldg(t0 + o) + __ldg(t1 + o) + __ldg(t2 + o);
        s = fmaf(__ldg(mask + g * LM + l), acc, s);
    }
    gul[i] = 0.25f * s;
}

// ---------------- gate MLP; g_emb = 0.25*(gsum+gl2) inline ----------------
__global__ void k_gate(float* __restrict__ w, const float* __restrict__ gsum,
                       const float* __restrict__ gl2, const float* __restrict__ gul,
                       const float* __restrict__ w1, const float* __restrict__ b1,
                       const float* __restrict__ w2, const float* __restrict__ b2) {
    int wid = (blockIdx.x * blockDim.x + threadIdx.x) >> 5;
    int lane = threadIdx.x & 31;
    if (wid >= 2 * G_N) return;
    float xd;
    if (wid < G_N) {
        size_t o = (size_t)wid * 32 + lane;
        xd = 0.25f * (__ldg(gsum + o) + __ldg(gl2 + o));
    } else {
        xd = __ldg(gul + (size_t)(wid - G_N) * 32 + lane);
    }
    float h = b1[lane];
    #pragma unroll
    for (int d = 0; d < 32; d++) {
        float a = __shfl_sync(0xffffffffu, xd, d);
        h = fmaf(a, __ldg(w1 + d * 32 + lane), h);
    }
    h = fmaxf(h, 0.f);
    float t = h * __ldg(w2 + lane);
    #pragma unroll
    for (int o = 16; o > 0; o >>= 1) t += __shfl_xor_sync(0xffffffffu, t, o);
    if (lane == 0) w[wid] = 1.f / (1.f + expf(-(t + b2[0])));
}

__global__ void k_combine(float* __restrict__ gf, const float* __restrict__ w,
                          const float* __restrict__ gsum, const float* __restrict__ gl2,
                          const float* __restrict__ gul) {
    int i = blockIdx.x * blockDim.x + threadIdx.x;
    if (i >= G_N * 32) return;
    int g = i >> 5;
    gf[i] = w[g] * 0.25f * (gsum[i] + gl2[i]) + w[G_N + g] * gul[i];
}

// ---------------- predict MLP; iacc = 0.25*(giis+yi+im) inline ----------------
__global__ void k_pred(float* __restrict__ out, const int* __restrict__ gin,
                       const int* __restrict__ iin, const float* __restrict__ gf,
                       const float* __restrict__ t0, const float* __restrict__ t1,
                       const float* __restrict__ t2,
                       const float* __restrict__ pw1, const float* __restrict__ pb1,
                       const float* __restrict__ pw2, const float* __restrict__ pb2) {
    int wid = (blockIdx.x * blockDim.x + threadIdx.x) >> 5;
    int lane = threadIdx.x & 31;
    if (wid >= B_N) return;
    int g = __ldg(gin + wid), it = __ldg(iin + wid);
    size_t o = ((size_t)it << 5) + lane;
    float ia = 0.25f * (__ldg(t0 + o) + __ldg(t1 + o) + __ldg(t2 + o));
    float e = __ldg(gf + (size_t)g * 32 + lane) * ia;
    float s = 0.f;
    #pragma unroll
    for (int j = 0; j < 8; j++) {
        float p = e * __ldg(pw1 + lane * 8 + j);
        #pragma unroll
        for (int o2 = 16; o2 > 0; o2 >>= 1) p += __shfl_xor_sync(0xffffffffu, p, o2);
        s += fmaxf(p + pb1[j], 0.f) * pw2[j];
    }
    if (lane == 0) out[wid] = 1.f / (1.f + expf(-(s + pb2[0])));
}

// ---------------- host driver ----------------
static inline int cdiv(int a, int b) { return (a + b - 1) / b; }

extern "C" void kernel_launch(void* const* d_in, const int* in_sizes, int n_in,
                              void* d_out, int out_size) {
    const int*   gin  = (const int*)  d_in[0];
    const int*   iin  = (const int*)  d_in[1];
    const float* uemb = (const float*)d_in[2];
    const float* gemb = (const float*)d_in[3];
    const float* iemb = (const float*)d_in[4];
    const int*   ui_r = (const int*)  d_in[5];
    const int*   ui_c = (const int*)  d_in[6];
    const float* ui_v = (const float*)d_in[7];
    const int*   gi_r = (const int*)  d_in[8];
    const int*   gi_c = (const int*)  d_in[9];
    const float* gi_v = (const float*)d_in[10];
    const float* ovu  = (const float*)d_in[11];
    const float* ovi  = (const float*)d_in[12];
    const int*   agu  = (const int*)  d_in[13];
    const float* agm  = (const float*)d_in[14];
    const float* gw1  = (const float*)d_in[15];
    const float* gb1  = (const float*)d_in[16];
    const float* gw2  = (const float*)d_in[17];
    const float* gb2  = (const float*)d_in[18];
    const float* pw1  = (const float*)d_in[19];
    const float* pb1  = (const float*)d_in[20];
    const float* pw2  = (const float*)d_in[21];
    const float* pb2  = (const float*)d_in[22];
    float* out = (float*)d_out;
    const int nnz_ui = in_sizes[5];
    const int nnz_gi = in_sizes[8];

    float* S = nullptr;
    cudaGetSymbolAddress((void**)&S, d_scratch);

    const int TPB = 256;
    int spmm_ui_grid = cdiv(nnz_ui * 4, TPB);   // 8 edges per warp
    int spmm_gi_grid = cdiv(nnz_gi * 4, TPB);

    cudaStream_t s2;
    cudaStreamCreateWithFlags(&s2, cudaStreamNonBlocking);
    cudaEvent_t evFork, evJoin;
    cudaEventCreateWithFlags(&evFork, cudaEventDisableTiming);
    cudaEventCreateWithFlags(&evJoin, cudaEventDisableTiming);

    // single zero of all accumulation buffers (contiguous region)
    k_zero4<<<cdiv(984000,TPB),TPB>>>((float4*)S, 984000);

    // ======== UI graph conv: l1 -> UI_B, l2 -> UI_A, l3 -> UI_C ========
    k_spmm<<<spmm_ui_grid,TPB>>>(ui_r, ui_c, ui_v, nnz_ui, uemb, iemb, U_N,
                                 S + OFF_UI_B, U_N + I_N);
    k_spmm<<<spmm_ui_grid,TPB>>>(ui_r, ui_c, ui_v, nnz_ui,
                                 S + OFF_UI_B, S + OFF_UI_B + U_N*32, U_N,
                                 S + OFF_UI_A, U_N + I_N);
    k_spmm<<<spmm_ui_grid,TPB>>>(ui_r, ui_c, ui_v, nnz_ui,
                                 S + OFF_UI_A, S + OFF_UI_A + U_N*32, U_N,
                                 S + OFF_UI_C, U_N + I_N);
    k_comb_ui<<<cdiv(168000,TPB),TPB>>>(S, (const float4*)uemb,
                                        (const float4*)iemb, (const float4*)gemb);

    // ---- fork: user social MM chain on s2 ----
    cudaEventRecord(evFork, 0);
    cudaStreamWaitEvent(s2, evFork, 0);
    {
        dim3 g(cdiv(U_N, 128), 8);
        k_mm_tc<<<g, 256, 0, s2>>>(ovu, S + OFF_USUM, S + OFF_YS, U_N);
        k_mm_tc<<<g, 256, 0, s2>>>(ovu, S + OFF_YS,   S + OFF_UM, U_N);
    }

    // ======== GI graph conv on stream 0 ========
    k_spmm<<<spmm_gi_grid,TPB>>>(gi_r, gi_c, gi_v, nnz_gi, gemb, S + OFF_IEU, G_N,
                                 S + OFF_GI_B, G_N + I_N);
    k_spmm<<<spmm_gi_grid,TPB>>>(gi_r, gi_c, gi_v, nnz_gi,
                                 S + OFF_GI_B, S + OFF_GI_B + G_N*32, G_N,
                                 S + OFF_GI_A, G_N + I_N);
    k_spmm<<<spmm_gi_grid,TPB>>>(gi_r, gi_c, gi_v, nnz_gi,
                                 S + OFF_GI_A, S + OFF_GI_A + G_N*32, G_N,
                                 S + OFF_GI_C, G_N + I_N);
    k_spmm<<<spmm_gi_grid,TPB>>>(gi_r, gi_c, gi_v, nnz_gi, gemb, iemb, G_N,
                                 S + OFF_GSUM, G_N);
    k_spmm<<<spmm_gi_grid,TPB>>>(gi_r, gi_c, gi_v, nnz_gi, gemb, S + OFF_UI_A + U_N*32,
                                 G_N, S + OFF_GSUM, G_N);
    k_comb_gi<<<cdiv(64000,TPB),TPB>>>(S);

    // ======== item social MM chain on stream 0 ========
    {
        dim3 g(cdiv(I_N, 128), 8);
        k_mm_tc<<<g, 256>>>(ovi, S + OFF_GIIS, S + OFF_YI, I_N);
        k_mm_tc<<<g, 256>>>(ovi, S + OFF_YI,   S + OFF_IM, I_N);
    }

    // ---- join ----
    cudaEventRecord(evJoin, s2);
    cudaStreamWaitEvent(0, evJoin, 0);

    // ======== pooling, gate, predict ========
    k_gul<<<cdiv(G_N*32, TPB), TPB>>>(S + OFF_GUL, agu, agm,
                                      S + OFF_USUM, S + OFF_YS, S + OFF_UM);
    k_gate<<<cdiv(2*G_N*32, TPB), TPB>>>(S + OFF_W, S + OFF_GSUM, S + OFF_GI_A,
                                         S + OFF_GUL, gw1, gb1, gw2, gb2);
    k_combine<<<cdiv(G_N*32, TPB), TPB>>>(S + OFF_GF, S + OFF_W, S + OFF_GSUM,
                                          S + OFF_GI_A, S + OFF_GUL);
    k_pred<<<cdiv(B_N*32, TPB), TPB>>>(out, gin, iin, S + OFF_GF,
                                       S + OFF_GIIS, S + OFF_YI, S + OFF_IM,
                                       pw1, pb1, pw2, pb2);

    cudaEventDestroy(evFork);
    cudaEventDestroy(evJoin);
    cudaStreamDestroy(s2);
}

// round 14
// speedup vs baseline: 1.3324x; 1.1166x over previous
#include <cuda_runtime.h>
#include <cuda_bf16.h>
#include <cstdint>
#include <math.h>

// ---------------- problem constants ----------------
#define U_N   10000
#define G_N   3000
#define I_N   8000
#define B_N   4096
#define LM    20

// ---------------- scratch layout (floats) ----------------
constexpr int OFF_UI_A = 0;        // 576000  UI l2
constexpr int OFF_UI_B = 576000;   // 576000  UI l1
constexpr int OFF_UI_C = 1152000;  // 576000  UI l3
constexpr int OFF_GI_A = 1728000;  // 352000  GI l2
constexpr int OFF_GI_B = 2080000;  // 352000  GI l1
constexpr int OFF_GI_C = 2432000;  // 352000  GI l3
constexpr int OFF_YS   = 2784000;  // 320000  user social term 1
constexpr int OFF_UM   = 3104000;  // 320000  user social term 2
constexpr int OFF_YI   = 3424000;  // 256000  item social term 1
constexpr int OFF_IM   = 3680000;  // 256000  item social term 2
// end of zeroed region (3936000)
constexpr int OFF_USUM = 3936000;  // 320000
constexpr int OFF_IEU  = 4256000;  // 256000
constexpr int OFF_GIIS = 4512000;  // 256000
constexpr int OFF_GSUM = 4768000;  // 96000
constexpr int OFF_GUL  = 4864000;  // 96000
constexpr int OFF_W    = 4960000;  // 6400
constexpr int OFF_GF   = 4966400;  // 96000
constexpr int SCRATCH_TOTAL = 5062400;

__device__ float d_scratch[SCRATCH_TOTAL];

// ---------------- elementwise helpers ----------------
__global__ void k_zero4(float4* p, int n4) {
    int i = blockIdx.x * blockDim.x + threadIdx.x;
    if (i < n4) p[i] = make_float4(0.f, 0.f, 0.f, 0.f);
}

__device__ __forceinline__ float4 add4(float4 a, float4 b) {
    return make_float4(a.x+b.x, a.y+b.y, a.z+b.z, a.w+b.w);
}
__device__ __forceinline__ float4 mul4(float4 a, float s) {
    return make_float4(a.x*s, a.y*s, a.z*s, a.w*s);
}

__global__ void k_comb_ui(float* __restrict__ S, const float4* __restrict__ uemb,
                          const float4* __restrict__ iemb, const float4* __restrict__ gemb) {
    int i = blockIdx.x * blockDim.x + threadIdx.x;
    const float4* A = (const float4*)(S + OFF_UI_A);
    const float4* B = (const float4*)(S + OFF_UI_B);
    const float4* C = (const float4*)(S + OFF_UI_C);
    if (i < 80000) {
        float4 s = add4(add4(uemb[i], B[i]), add4(A[i], C[i]));
        ((float4*)(S + OFF_USUM))[i] = s;
    } else if (i < 144000) {
        int j = i - 80000;
        float4 s = add4(add4(iemb[j], B[i]), add4(A[i], C[i]));
        ((float4*)(S + OFF_IEU))[j] = mul4(s, 0.25f);
    } else if (i < 168000) {
        int j = i - 144000;
        ((float4*)(S + OFF_GSUM))[j] = gemb[j];
    }
}

__global__ void k_comb_gi(float* __restrict__ S) {
    int i = blockIdx.x * blockDim.x + threadIdx.x;
    if (i >= 64000) return;
    int j = G_N * 8 + i;
    const float4* A = (const float4*)(S + OFF_GI_A);
    const float4* B = (const float4*)(S + OFF_GI_B);
    const float4* C = (const float4*)(S + OFF_GI_C);
    const float4* E = (const float4*)(S + OFF_IEU);
    ((float4*)(S + OFF_GIIS))[i] = add4(add4(E[i], B[j]), add4(A[j], C[j]));
}

// ---------------- COO SpMM: 8 edges/warp, 2-way ILP per lane ----------------
__device__ __forceinline__ void red4(float* p, float a, float b, float c, float d) {
    asm volatile("red.global.add.v4.f32 [%0], {%1, %2, %3, %4};"
                 :: "l"(p), "f"(a), "f"(b), "f"(c), "f"(d) : "memory");
}
__global__ void k_spmm(const int* __restrict__ rows, const int* __restrict__ cols,
                       const float* __restrict__ vals, int nnz,
                       const float* __restrict__ x0, const float* __restrict__ x1,
                       int split, float* __restrict__ out, int row_limit) {
    int gw = (blockIdx.x * blockDim.x + threadIdx.x) >> 5;
    int lane = threadIdx.x & 31;
    int e0 = gw << 3;
    if (e0 >= nnz) return;
    int ld = 0;
    int half = lane >> 4;
    int hl = lane & 15;
    int which = hl >> 2;
    int j4 = e0 + half * 4 + (hl & 3);
    if (which < 3 && j4 < nnz) {
        if (which == 0)      ld = __ldg(rows + j4);
        else if (which == 1) ld = __ldg(cols + j4);
        else                 ld = __float_as_int(__ldg(vals + j4));
    }
    int subw = lane >> 3;
    int l4   = (lane & 7) << 2;
    int rA =                 __shfl_sync(0xffffffffu, ld, subw);
    int cA =                 __shfl_sync(0xffffffffu, ld, 4 + subw);
    float vA = __int_as_float(__shfl_sync(0xffffffffu, ld, 8 + subw));
    int rB =                 __shfl_sync(0xffffffffu, ld, 16 + subw);
    int cB =                 __shfl_sync(0xffffffffu, ld, 20 + subw);
    float vB = __int_as_float(__shfl_sync(0xffffffffu, ld, 24 + subw));
    int eA = e0 + subw, eB = e0 + 4 + subw;
    bool doA = (eA < nnz) && (rA < row_limit);
    bool doB = (eB < nnz) && (rB < row_limit);
    float4 xa, xb;
    if (doA) {
        const float* s = (cA < split) ? x0 + ((size_t)cA << 5)
                                      : x1 + ((size_t)(cA - split) << 5);
        xa = *(const float4*)(s + l4);
    }
    if (doB) {
        const float* s = (cB < split) ? x0 + ((size_t)cB << 5)
                                      : x1 + ((size_t)(cB - split) << 5);
        xb = *(const float4*)(s + l4);
    }
    if (doA) red4(out + ((size_t)rA << 5) + l4, vA*xa.x, vA*xa.y, vA*xa.z, vA*xa.w);
    if (doB) red4(out + ((size_t)rB << 5) + l4, vB*xb.x, vB*xb.y, vB*xb.z, vB*xb.w);
}

// ---------------- tensor-core dense MM: y += A@x, double-buffered ----------------
// Chunk body reordered to sync -> prefetch -> mma(s) -> convert(s^1):
// convert of early-finishing warps overlaps the tensor tail of laggards.
#define MMKC 32
#define MALD 40
#define A_STAGE (128 * MALD)
#define X_STAGE (MMKC * MALD)

__device__ __forceinline__ uint32_t cvta_s(const void* p) {
    return (uint32_t)__cvta_generic_to_shared(p);
}
__device__ __forceinline__ void ldm_x4(uint32_t* r, uint32_t addr) {
    asm volatile("ldmatrix.sync.aligned.m8n8.x4.shared.b16 {%0,%1,%2,%3}, [%4];"
                 : "=r"(r[0]), "=r"(r[1]), "=r"(r[2]), "=r"(r[3]) : "r"(addr));
}
__device__ __forceinline__ void ldm_x4_t(uint32_t* r, uint32_t addr) {
    asm volatile("ldmatrix.sync.aligned.m8n8.x4.trans.shared.b16 {%0,%1,%2,%3}, [%4];"
                 : "=r"(r[0]), "=r"(r[1]), "=r"(r[2]), "=r"(r[3]) : "r"(addr));
}
__device__ __forceinline__ void mma_bf16(float* d, const uint32_t* a,
                                         uint32_t b0, uint32_t b1) {
    asm volatile("mma.sync.aligned.m16n8k16.row.col.f32.bf16.bf16.f32 "
                 "{%0,%1,%2,%3}, {%4,%5,%6,%7}, {%8,%9}, {%0,%1,%2,%3};"
                 : "+f"(d[0]), "+f"(d[1]), "+f"(d[2]), "+f"(d[3])
                 : "r"(a[0]), "r"(a[1]), "r"(a[2]), "r"(a[3]), "r"(b0), "r"(b1));
}
__device__ __forceinline__ void red2(float* p, float a, float b) {
    asm volatile("red.global.add.v2.f32 [%0], {%1, %2};"
                 :: "l"(p), "f"(a), "f"(b) : "memory");
}
__device__ __forceinline__ void st_split4(float4 v, __nv_bfloat16* hd, __nv_bfloat16* ldst) {
    uint32_t x0 = __float_as_uint(v.x), x1 = __float_as_uint(v.y);
    uint32_t x2 = __float_as_uint(v.z), x3 = __float_as_uint(v.w);
    uint32_t h01, h23;
    asm("prmt.b32 %0, %1, %2, 0x7632;" : "=r"(h01) : "r"(x0), "r"(x1));
    asm("prmt.b32 %0, %1, %2, 0x7632;" : "=r"(h23) : "r"(x2), "r"(x3));
    float l0 = v.x - __uint_as_float(x0 & 0xFFFF0000u);
    float l1 = v.y - __uint_as_float(x1 & 0xFFFF0000u);
    float l2 = v.z - __uint_as_float(x2 & 0xFFFF0000u);
    float l3 = v.w - __uint_as_float(x3 & 0xFFFF0000u);
    uint32_t lo01, lo23;
    asm("prmt.b32 %0, %1, %2, 0x7632;" : "=r"(lo01)
        : "r"(__float_as_uint(l0)), "r"(__float_as_uint(l1)));
    asm("prmt.b32 %0, %1, %2, 0x7632;" : "=r"(lo23)
        : "r"(__float_as_uint(l2)), "r"(__float_as_uint(l3)));
    *(uint2*)hd   = make_uint2(h01, h23);
    *(uint2*)ldst = make_uint2(lo01, lo23);
}

__global__ void __launch_bounds__(256, 3)
k_mm_tc(const float* __restrict__ A, const float* __restrict__ x,
        float* __restrict__ y, int n) {
    __shared__ __nv_bfloat16 Ah[2][A_STAGE], Al[2][A_STAGE];
    __shared__ __nv_bfloat16 Xh[2][X_STAGE], Xl[2][X_STAGE];
    int tid = threadIdx.x;
    int warp = tid >> 5, lane = tid & 31;
    int m0 = blockIdx.x * 128;

    int nchunks = (n + MMKC - 1) / MMKC;
    int per = (nchunks + gridDim.y - 1) / gridDim.y;
    int ci0 = blockIdx.y * per;
    int ci1 = min(nchunks, ci0 + per);

    float acc[4][4];
    #pragma unroll
    for (int f = 0; f < 4; f++)
        #pragma unroll
        for (int j = 0; j < 4; j++) acc[f][j] = 0.f;

    uint32_t aAddrH0 = cvta_s(&Ah[0][(warp * 16 + (lane & 15)) * MALD + ((lane >> 4) << 3)]);
    uint32_t aAddrL0 = cvta_s(&Al[0][(warp * 16 + (lane & 15)) * MALD + ((lane >> 4) << 3)]);
    uint32_t xBaseH0 = cvta_s(&Xh[0][(lane & 15) * MALD + ((lane >> 4) << 3)]);
    uint32_t xBaseL0 = cvta_s(&Xl[0][(lane & 15) * MALD + ((lane >> 4) << 3)]);

    int ar = tid >> 1, ahalf = tid & 1;
    int xr = tid >> 3, xc = (tid & 7) << 2;
    int gr = m0 + ar;
    const float* Arow = A + (size_t)gr * n + ahalf * 16;

    float4 aR[4], xR;
    const float4 Z4 = make_float4(0.f, 0.f, 0.f, 0.f);

    // ---- prologue: load + convert chunk ci0 into stage ci0&1 ----
    if (ci0 < ci1) {
        int k0 = ci0 * MMKC;
        xR = Z4;
        if (k0 + xr < n) xR = *(const float4*)(x + (size_t)(k0 + xr) * 32 + xc);
        #pragma unroll
        for (int j = 0; j < 4; j++) {
            int col = ahalf * 16 + j * 4;
            aR[j] = Z4;
            if (gr < n && (k0 + col + 4) <= n) aR[j] = *(const float4*)(Arow + k0 + j * 4);
        }
        int s = ci0 & 1;
        st_split4(xR, &Xh[s][xr * MALD + xc], &Xl[s][xr * MALD + xc]);
        #pragma unroll
        for (int j = 0; j < 4; j++) {
            int col = ahalf * 16 + j * 4;
            st_split4(aR[j], &Ah[s][ar * MALD + col], &Al[s][ar * MALD + col]);
        }
    }

    for (int ci = ci0; ci < ci1; ci++) {
        int s = ci & 1;
        __syncthreads();   // orders convert(s) [prev body] before mma(s) reads, and
                           // convert(s^1) [this body] after mma(s^1) two chunks ago
        bool more = (ci + 1 < ci1);
        // issue prefetch for chunk ci+1 (consumed by convert at end of this body)
        if (more) {
            int k0 = (ci + 1) * MMKC;
            xR = Z4;
            if (k0 + xr < n) xR = *(const float4*)(x + (size_t)(k0 + xr) * 32 + xc);
            #pragma unroll
            for (int j = 0; j < 4; j++) {
                int col = ahalf * 16 + j * 4;
                aR[j] = Z4;
                if (gr < n && (k0 + col + 4) <= n) aR[j] = *(const float4*)(Arow + k0 + j * 4);
            }
        }
        // MMA on stage s
        uint32_t aOff = (uint32_t)s * (A_STAGE * 2);
        uint32_t xOff = (uint32_t)s * (X_STAGE * 2);
        #pragma unroll
        for (int ks = 0; ks < MMKC; ks += 16) {
            uint32_t afh[4], afl[4];
            ldm_x4(afh, aAddrH0 + aOff + ks * 2);
            ldm_x4(afl, aAddrL0 + aOff + ks * 2);
            #pragma unroll
            for (int np = 0; np < 2; np++) {
                uint32_t bh[4], bl[4];
                uint32_t off = (uint32_t)(ks * MALD + np * 16) * 2;
                ldm_x4_t(bh, xBaseH0 + xOff + off);
                ldm_x4_t(bl, xBaseL0 + xOff + off);
                mma_bf16(acc[np * 2 + 0], afh, bh[0], bh[1]);
                mma_bf16(acc[np * 2 + 1], afh, bh[2], bh[3]);
                mma_bf16(acc[np * 2 + 0], afh, bl[0], bl[1]);
                mma_bf16(acc[np * 2 + 1], afh, bl[2], bl[3]);
                mma_bf16(acc[np * 2 + 0], afl, bh[0], bh[1]);
                mma_bf16(acc[np * 2 + 1], afl, bh[2], bh[3]);
            }
        }
        // convert chunk ci+1 into the other stage (overlaps other warps' mma tail)
        if (more) {
            st_split4(xR, &Xh[s^1][xr * MALD + xc], &Xl[s^1][xr * MALD + xc]);
            #pragma unroll
            for (int j = 0; j < 4; j++) {
                int col = ahalf * 16 + j * 4;
                st_split4(aR[j], &Ah[s^1][ar * MALD + col], &Al[s^1][ar * MALD + col]);
            }
        }
    }

    int gr8 = lane >> 2, cc = (lane & 3) * 2;
    #pragma unroll
    for (int f = 0; f < 4; f++) {
        int nc = f * 8 + cc;
        int r0 = m0 + warp * 16 + gr8;
        int r1 = r0 + 8;
        if (r0 < n) red2(y + (size_t)r0 * 32 + nc, acc[f][0], acc[f][1]);
        if (r1 < n) red2(y + (size_t)r1 * 32 + nc, acc[f][2], acc[f][3]);
    }
}

// ---------------- group_userlayer ----------------
__global__ void k_gul(float* __restrict__ gul, const int* __restrict__ users,
                      const float* __restrict__ mask, const float* __restrict__ t0,
                      const float* __restrict__ t1, const float* __restrict__ t2) {
    int i = blockIdx.x * blockDim.x + threadIdx.x;
    if (i >= G_N * 32) return;
    int g = i >> 5, d = i & 31;
    float s = 0.f;
    #pragma unroll
    for (int l = 0; l < LM; l++) {
        int u = __ldg(users + g * LM + l);
        size_t o = ((size_t)u << 5) + d;
        float acc = __ldg(t0 + o) + __ldg(t1 + o) + __ldg(t2 + o);
        s = fmaf(__ldg(mask + g * LM + l), acc, s);
    }
    gul[i] = 0.25f * s;
}

// ---------------- gate MLP ----------------
__global__ void k_gate(float* __restrict__ w, const float* __restrict__ gsum,
                       const float* __restrict__ gl2, const float* __restrict__ gul,
                       const float* __restrict__ w1, const float* __restrict__ b1,
                       const float* __restrict__ w2, const float* __restrict__ b2) {
    int wid = (blockIdx.x * blockDim.x + threadIdx.x) >> 5;
    int lane = threadIdx.x & 31;
    if (wid >= 2 * G_N) return;
    float xd;
    if (wid < G_N) {
        size_t o = (size_t)wid * 32 + lane;
        xd = 0.25f * (__ldg(gsum + o) + __ldg(gl2 + o));
    } else {
        xd = __ldg(gul + (size_t)(wid - G_N) * 32 + lane);
    }
    float h = b1[lane];
    #pragma unroll
    for (int d = 0; d < 32; d++) {
        float a = __shfl_sync(0xffffffffu, xd, d);
        h = fmaf(a, __ldg(w1 + d * 32 + lane), h);
    }
    h = fmaxf(h, 0.f);
    float t = h * __ldg(w2 + lane);
    #pragma unroll
    for (int o = 16; o > 0; o >>= 1) t += __shfl_xor_sync(0xffffffffu, t, o);
    if (lane == 0) w[wid] = 1.f / (1.f + expf(-(t + b2[0])));
}

__global__ void k_combine(float* __restrict__ gf, const float* __restrict__ w,
                          const float* __restrict__ gsum, const float* __restrict__ gl2,
                          const float* __restrict__ gul) {
    int i = blockIdx.x * blockDim.x + threadIdx.x;
    if (i >= G_N * 32) return;
    int g = i >> 5;
    gf[i] = w[g] * 0.25f * (gsum[i] + gl2[i]) + w[G_N + g] * gul[i];
}

// ---------------- predict MLP ----------------
__global__ void k_pred(float* __restrict__ out, const int* __restrict__ gin,
                       const int* __restrict__ iin, const float* __restrict__ gf,
                       const float* __restrict__ t0, const float* __restrict__ t1,
                       const float* __restrict__ t2,
                       const float* __restrict__ pw1, const float* __restrict__ pb1,
                       const float* __restrict__ pw2, const float* __restrict__ pb2) {
    int wid = (blockIdx.x * blockDim.x + threadIdx.x) >> 5;
    int lane = threadIdx.x & 31;
    if (wid >= B_N) return;
    int g = __ldg(gin + wid), it = __ldg(iin + wid);
    size_t o = ((size_t)it << 5) + lane;
    float ia = 0.25f * (__ldg(t0 + o) + __ldg(t1 + o) + __ldg(t2 + o));
    float e = __ldg(gf + (size_t)g * 32 + lane) * ia;
    float s = 0.f;
    #pragma unroll
    for (int j = 0; j < 8; j++) {
        float p = e * __ldg(pw1 + lane * 8 + j);
        #pragma unroll
        for (int o2 = 16; o2 > 0; o2 >>= 1) p += __shfl_xor_sync(0xffffffffu, p, o2);
        s += fmaxf(p + pb1[j], 0.f) * pw2[j];
    }
    if (lane == 0) out[wid] = 1.f / (1.f + expf(-(s + pb2[0])));
}

// ---------------- host driver ----------------
static inline int cdiv(int a, int b) { return (a + b - 1) / b; }

extern "C" void kernel_launch(void* const* d_in, const int* in_sizes, int n_in,
                              void* d_out, int out_size) {
    const int*   gin  = (const int*)  d_in[0];
    const int*   iin  = (const int*)  d_in[1];
    const float* uemb = (const float*)d_in[2];
    const float* gemb = (const float*)d_in[3];
    const float* iemb = (const float*)d_in[4];
    const int*   ui_r = (const int*)  d_in[5];
    const int*   ui_c = (const int*)  d_in[6];
    const float* ui_v = (const float*)d_in[7];
    const int*   gi_r = (const int*)  d_in[8];
    const int*   gi_c = (const int*)  d_in[9];
    const float* gi_v = (const float*)d_in[10];
    const float* ovu  = (const float*)d_in[11];
    const float* ovi  = (const float*)d_in[12];
    const int*   agu  = (const int*)  d_in[13];
    const float* agm  = (const float*)d_in[14];
    const float* gw1  = (const float*)d_in[15];
    const float* gb1  = (const float*)d_in[16];
    const float* gw2  = (const float*)d_in[17];
    const float* gb2  = (const float*)d_in[18];
    const float* pw1  = (const float*)d_in[19];
    const float* pb1  = (const float*)d_in[20];
    const float* pw2  = (const float*)d_in[21];
    const float* pb2  = (const float*)d_in[22];
    float* out = (float*)d_out;
    const int nnz_ui = in_sizes[5];
    const int nnz_gi = in_sizes[8];

    float* S = nullptr;
    cudaGetSymbolAddress((void**)&S, d_scratch);

    const int TPB = 256;
    int spmm_ui_grid = cdiv(nnz_ui * 4, TPB);
    int spmm_gi_grid = cdiv(nnz_gi * 4, TPB);

    cudaStream_t s2;
    cudaStreamCreateWithFlags(&s2, cudaStreamNonBlocking);
    cudaEvent_t evFork, evJoin;
    cudaEventCreateWithFlags(&evFork, cudaEventDisableTiming);
    cudaEventCreateWithFlags(&evJoin, cudaEventDisableTiming);

    // single zero of all accumulation buffers
    k_zero4<<<cdiv(984000,TPB),TPB>>>((float4*)S, 984000);

    // ======== UI graph conv ========
    k_spmm<<<spmm_ui_grid,TPB>>>(ui_r, ui_c, ui_v, nnz_ui, uemb, iemb, U_N,
                                 S + OFF_UI_B, U_N + I_N);
    k_spmm<<<spmm_ui_grid,TPB>>>(ui_r, ui_c, ui_v, nnz_ui,
                                 S + OFF_UI_B, S + OFF_UI_B + U_N*32, U_N,
                                 S + OFF_UI_A, U_N + I_N);
    k_spmm<<<spmm_ui_grid,TPB>>>(ui_r, ui_c, ui_v, nnz_ui,
                                 S + OFF_UI_A, S + OFF_UI_A + U_N*32, U_N,
                                 S + OFF_UI_C, U_N + I_N);
    k_comb_ui<<<cdiv(168000,TPB),TPB>>>(S, (const float4*)uemb,
                                        (const float4*)iemb, (const float4*)gemb);

    // ---- fork: user social MM chain on s2 ----
    cudaEventRecord(evFork, 0);
    cudaStreamWaitEvent(s2, evFork, 0);
    {
        dim3 g(cdiv(U_N, 128), 11);
        k_mm_tc<<<g, 256, 0, s2>>>(ovu, S + OFF_USUM, S + OFF_YS, U_N);
        k_mm_tc<<<g, 256, 0, s2>>>(ovu, S + OFF_YS,   S + OFF_UM, U_N);
    }

    // ======== GI graph conv on stream 0 ========
    k_spmm<<<spmm_gi_grid,TPB>>>(gi_r, gi_c, gi_v, nnz_gi, gemb, S + OFF_IEU, G_N,
                                 S + OFF_GI_B, G_N + I_N);
    k_spmm<<<spmm_gi_grid,TPB>>>(gi_r, gi_c, gi_v, nnz_gi,
                                 S + OFF_GI_B, S + OFF_GI_B + G_N*32, G_N,
                                 S + OFF_GI_A, G_N + I_N);
    k_spmm<<<spmm_gi_grid,TPB>>>(gi_r, gi_c, gi_v, nnz_gi,
                                 S + OFF_GI_A, S + OFF_GI_A + G_N*32, G_N,
                                 S + OFF_GI_C, G_N + I_N);
    k_spmm<<<spmm_gi_grid,TPB>>>(gi_r, gi_c, gi_v, nnz_gi, gemb, iemb, G_N,
                                 S + OFF_GSUM, G_N);
    k_spmm<<<spmm_gi_grid,TPB>>>(gi_r, gi_c, gi_v, nnz_gi, gemb, S + OFF_UI_A + U_N*32,
                                 G_N, S + OFF_GSUM, G_N);
    k_comb_gi<<<cdiv(64000,TPB),TPB>>>(S);

    // ======== item social MM chain on stream 0 ========
    {
        dim3 g(cdiv(I_N, 128), 14);
        k_mm_tc<<<g, 256>>>(ovi, S + OFF_GIIS, S + OFF_YI, I_N);
        k_mm_tc<<<g, 256>>>(ovi, S + OFF_YI,   S + OFF_IM, I_N);
    }

    // ---- join ----
    cudaEventRecord(evJoin, s2);
    cudaStreamWaitEvent(0, evJoin, 0);

    // ======== pooling, gate, predict ========
    k_gul<<<cdiv(G_N*32, TPB), TPB>>>(S + OFF_GUL, agu, agm,
                                      S + OFF_USUM, S + OFF_YS, S + OFF_UM);
    k_gate<<<cdiv(2*G_N*32, TPB), TPB>>>(S + OFF_W, S + OFF_GSUM, S + OFF_GI_A,
                                         S + OFF_GUL, gw1, gb1, gw2, gb2);
    k_combine<<<cdiv(G_N*32, TPB), TPB>>>(S + OFF_GF, S + OFF_W, S + OFF_GSUM,
                                          S + OFF_GI_A, S + OFF_GUL);
    k_pred<<<cdiv(B_N*32, TPB), TPB>>>(out, gin, iin, S + OFF_GF,
                                       S + OFF_GIIS, S + OFF_YI, S + OFF_IM,
                                       pw1, pb1, pw2, pb2);

    cudaEventDestroy(evFork);
    cudaEventDestroy(evJoin);
    cudaStreamDestroy(s2);
}

// round 15
// speedup vs baseline: 1.4853x; 1.1148x over previous
#include <cuda_runtime.h>
#include <cuda_bf16.h>
#include <cstdint>
#include <math.h>

// ---------------- problem constants ----------------
#define U_N   10000
#define G_N   3000
#define I_N   8000
#define B_N   4096
#define LM    20

// ---------------- scratch layout (floats) ----------------
constexpr int OFF_UI_A = 0;        // 576000  UI l2
constexpr int OFF_UI_B = 576000;   // 576000  UI l1
constexpr int OFF_UI_C = 1152000;  // 576000  UI l3
constexpr int OFF_GI_A = 1728000;  // 352000  GI l2
constexpr int OFF_GI_B = 2080000;  // 352000  GI l1
constexpr int OFF_GI_C = 2432000;  // 352000  GI l3
constexpr int OFF_YS   = 2784000;  // 320000  user social term 1
constexpr int OFF_UM   = 3104000;  // 320000  user social term 2
constexpr int OFF_YI   = 3424000;  // 256000  item social term 1
constexpr int OFF_IM   = 3680000;  // 256000  item social term 2
// end of zeroed region (3936000)
constexpr int OFF_USUM = 3936000;  // 320000
constexpr int OFF_IEU  = 4256000;  // 256000
constexpr int OFF_GIIS = 4512000;  // 256000
constexpr int OFF_GSUM = 4768000;  // 96000
constexpr int OFF_GUL  = 4864000;  // 96000
constexpr int OFF_W    = 4960000;  // 6400
constexpr int OFF_GF   = 4966400;  // 96000
constexpr int SCRATCH_TOTAL = 5062400;

__device__ float d_scratch[SCRATCH_TOTAL];

// ---------------- elementwise helpers ----------------
__global__ void k_zero4(float4* p, int n4) {
    int i = blockIdx.x * blockDim.x + threadIdx.x;
    if (i < n4) p[i] = make_float4(0.f, 0.f, 0.f, 0.f);
}

__device__ __forceinline__ float4 add4(float4 a, float4 b) {
    return make_float4(a.x+b.x, a.y+b.y, a.z+b.z, a.w+b.w);
}
__device__ __forceinline__ float4 mul4(float4 a, float s) {
    return make_float4(a.x*s, a.y*s, a.z*s, a.w*s);
}

__global__ void k_comb_ui(float* __restrict__ S, const float4* __restrict__ uemb,
                          const float4* __restrict__ iemb, const float4* __restrict__ gemb) {
    int i = blockIdx.x * blockDim.x + threadIdx.x;
    const float4* A = (const float4*)(S + OFF_UI_A);
    const float4* B = (const float4*)(S + OFF_UI_B);
    const float4* C = (const float4*)(S + OFF_UI_C);
    if (i < 80000) {
        float4 s = add4(add4(uemb[i], B[i]), add4(A[i], C[i]));
        ((float4*)(S + OFF_USUM))[i] = s;
    } else if (i < 144000) {
        int j = i - 80000;
        float4 s = add4(add4(iemb[j], B[i]), add4(A[i], C[i]));
        ((float4*)(S + OFF_IEU))[j] = mul4(s, 0.25f);
    } else if (i < 168000) {
        int j = i - 144000;
        ((float4*)(S + OFF_GSUM))[j] = gemb[j];
    }
}

__global__ void k_comb_gi(float* __restrict__ S) {
    int i = blockIdx.x * blockDim.x + threadIdx.x;
    if (i >= 64000) return;
    int j = G_N * 8 + i;
    const float4* A = (const float4*)(S + OFF_GI_A);
    const float4* B = (const float4*)(S + OFF_GI_B);
    const float4* C = (const float4*)(S + OFF_GI_C);
    const float4* E = (const float4*)(S + OFF_IEU);
    ((float4*)(S + OFF_GIIS))[i] = add4(add4(E[i], B[j]), add4(A[j], C[j]));
}

// ---------------- COO SpMM: 8 edges/warp, 2-way ILP per lane ----------------
__device__ __forceinline__ void red4(float* p, float a, float b, float c, float d) {
    asm volatile("red.global.add.v4.f32 [%0], {%1, %2, %3, %4};"
                 :: "l"(p), "f"(a), "f"(b), "f"(c), "f"(d) : "memory");
}
__global__ void k_spmm(const int* __restrict__ rows, const int* __restrict__ cols,
                       const float* __restrict__ vals, int nnz,
                       const float* __restrict__ x0, const float* __restrict__ x1,
                       int split, float* __restrict__ out, int row_limit) {
    int gw = (blockIdx.x * blockDim.x + threadIdx.x) >> 5;
    int lane = threadIdx.x & 31;
    int e0 = gw << 3;
    if (e0 >= nnz) return;
    int ld = 0;
    int half = lane >> 4;
    int hl = lane & 15;
    int which = hl >> 2;
    int j4 = e0 + half * 4 + (hl & 3);
    if (which < 3 && j4 < nnz) {
        if (which == 0)      ld = __ldg(rows + j4);
        else if (which == 1) ld = __ldg(cols + j4);
        else                 ld = __float_as_int(__ldg(vals + j4));
    }
    int subw = lane >> 3;
    int l4   = (lane & 7) << 2;
    int rA =                 __shfl_sync(0xffffffffu, ld, subw);
    int cA =                 __shfl_sync(0xffffffffu, ld, 4 + subw);
    float vA = __int_as_float(__shfl_sync(0xffffffffu, ld, 8 + subw));
    int rB =                 __shfl_sync(0xffffffffu, ld, 16 + subw);
    int cB =                 __shfl_sync(0xffffffffu, ld, 20 + subw);
    float vB = __int_as_float(__shfl_sync(0xffffffffu, ld, 24 + subw));
    int eA = e0 + subw, eB = e0 + 4 + subw;
    bool doA = (eA < nnz) && (rA < row_limit);
    bool doB = (eB < nnz) && (rB < row_limit);
    float4 xa, xb;
    if (doA) {
        const float* s = (cA < split) ? x0 + ((size_t)cA << 5)
                                      : x1 + ((size_t)(cA - split) << 5);
        xa = *(const float4*)(s + l4);
    }
    if (doB) {
        const float* s = (cB < split) ? x0 + ((size_t)cB << 5)
                                      : x1 + ((size_t)(cB - split) << 5);
        xb = *(const float4*)(s + l4);
    }
    if (doA) red4(out + ((size_t)rA << 5) + l4, vA*xa.x, vA*xa.y, vA*xa.z, vA*xa.w);
    if (doB) red4(out + ((size_t)rB << 5) + l4, vB*xb.x, vB*xb.y, vB*xb.z, vB*xb.w);
}

// ---------------- tensor-core dense MM: y += A@x ----------------
// 2-term split: acc = A_hi*(x_hi + x_lo). A truncated to bf16 (2 PRMT/float4,
// no lo stage); x keeps hi+lo correction. Double-buffered, body ordered
// sync -> prefetch -> mma(s) -> convert(s^1).
#define MMKC 32
#define MALD 40
#define A_STAGE (128 * MALD)
#define X_STAGE (MMKC * MALD)

__device__ __forceinline__ uint32_t cvta_s(const void* p) {
    return (uint32_t)__cvta_generic_to_shared(p);
}
__device__ __forceinline__ void ldm_x4(uint32_t* r, uint32_t addr) {
    asm volatile("ldmatrix.sync.aligned.m8n8.x4.shared.b16 {%0,%1,%2,%3}, [%4];"
                 : "=r"(r[0]), "=r"(r[1]), "=r"(r[2]), "=r"(r[3]) : "r"(addr));
}
__device__ __forceinline__ void ldm_x4_t(uint32_t* r, uint32_t addr) {
    asm volatile("ldmatrix.sync.aligned.m8n8.x4.trans.shared.b16 {%0,%1,%2,%3}, [%4];"
                 : "=r"(r[0]), "=r"(r[1]), "=r"(r[2]), "=r"(r[3]) : "r"(addr));
}
__device__ __forceinline__ void mma_bf16(float* d, const uint32_t* a,
                                         uint32_t b0, uint32_t b1) {
    asm volatile("mma.sync.aligned.m16n8k16.row.col.f32.bf16.bf16.f32 "
                 "{%0,%1,%2,%3}, {%4,%5,%6,%7}, {%8,%9}, {%0,%1,%2,%3};"
                 : "+f"(d[0]), "+f"(d[1]), "+f"(d[2]), "+f"(d[3])
                 : "r"(a[0]), "r"(a[1]), "r"(a[2]), "r"(a[3]), "r"(b0), "r"(b1));
}
__device__ __forceinline__ void red2(float* p, float a, float b) {
    asm volatile("red.global.add.v2.f32 [%0], {%1, %2};"
                 :: "l"(p), "f"(a), "f"(b) : "memory");
}
// A: truncate-pack hi only (2 PRMT per float4)
__device__ __forceinline__ void st_hi4(float4 v, __nv_bfloat16* hd) {
    uint32_t x0 = __float_as_uint(v.x), x1 = __float_as_uint(v.y);
    uint32_t x2 = __float_as_uint(v.z), x3 = __float_as_uint(v.w);
    uint32_t h01, h23;
    asm("prmt.b32 %0, %1, %2, 0x7632;" : "=r"(h01) : "r"(x0), "r"(x1));
    asm("prmt.b32 %0, %1, %2, 0x7632;" : "=r"(h23) : "r"(x2), "r"(x3));
    *(uint2*)hd = make_uint2(h01, h23);
}
// x: hi + lo correction
__device__ __forceinline__ void st_split4(float4 v, __nv_bfloat16* hd, __nv_bfloat16* ldst) {
    uint32_t x0 = __float_as_uint(v.x), x1 = __float_as_uint(v.y);
    uint32_t x2 = __float_as_uint(v.z), x3 = __float_as_uint(v.w);
    uint32_t h01, h23;
    asm("prmt.b32 %0, %1, %2, 0x7632;" : "=r"(h01) : "r"(x0), "r"(x1));
    asm("prmt.b32 %0, %1, %2, 0x7632;" : "=r"(h23) : "r"(x2), "r"(x3));
    float l0 = v.x - __uint_as_float(x0 & 0xFFFF0000u);
    float l1 = v.y - __uint_as_float(x1 & 0xFFFF0000u);
    float l2 = v.z - __uint_as_float(x2 & 0xFFFF0000u);
    float l3 = v.w - __uint_as_float(x3 & 0xFFFF0000u);
    uint32_t lo01, lo23;
    asm("prmt.b32 %0, %1, %2, 0x7632;" : "=r"(lo01)
        : "r"(__float_as_uint(l0)), "r"(__float_as_uint(l1)));
    asm("prmt.b32 %0, %1, %2, 0x7632;" : "=r"(lo23)
        : "r"(__float_as_uint(l2)), "r"(__float_as_uint(l3)));
    *(uint2*)hd   = make_uint2(h01, h23);
    *(uint2*)ldst = make_uint2(lo01, lo23);
}

__global__ void __launch_bounds__(256, 3)
k_mm_tc(const float* __restrict__ A, const float* __restrict__ x,
        float* __restrict__ y, int n) {
    __shared__ __nv_bfloat16 Ah[2][A_STAGE];
    __shared__ __nv_bfloat16 Xh[2][X_STAGE], Xl[2][X_STAGE];
    int tid = threadIdx.x;
    int warp = tid >> 5, lane = tid & 31;
    int m0 = blockIdx.x * 128;

    int nchunks = (n + MMKC - 1) / MMKC;
    int per = (nchunks + gridDim.y - 1) / gridDim.y;
    int ci0 = blockIdx.y * per;
    int ci1 = min(nchunks, ci0 + per);

    float acc[4][4];
    #pragma unroll
    for (int f = 0; f < 4; f++)
        #pragma unroll
        for (int j = 0; j < 4; j++) acc[f][j] = 0.f;

    uint32_t aAddrH0 = cvta_s(&Ah[0][(warp * 16 + (lane & 15)) * MALD + ((lane >> 4) << 3)]);
    uint32_t xBaseH0 = cvta_s(&Xh[0][(lane & 15) * MALD + ((lane >> 4) << 3)]);
    uint32_t xBaseL0 = cvta_s(&Xl[0][(lane & 15) * MALD + ((lane >> 4) << 3)]);

    int ar = tid >> 1, ahalf = tid & 1;
    int xr = tid >> 3, xc = (tid & 7) << 2;
    int gr = m0 + ar;
    const float* Arow = A + (size_t)gr * n + ahalf * 16;

    float4 aR[4], xR;
    const float4 Z4 = make_float4(0.f, 0.f, 0.f, 0.f);

    // ---- prologue: load + convert chunk ci0 ----
    if (ci0 < ci1) {
        int k0 = ci0 * MMKC;
        xR = Z4;
        if (k0 + xr < n) xR = *(const float4*)(x + (size_t)(k0 + xr) * 32 + xc);
        #pragma unroll
        for (int j = 0; j < 4; j++) {
            int col = ahalf * 16 + j * 4;
            aR[j] = Z4;
            if (gr < n && (k0 + col + 4) <= n) aR[j] = *(const float4*)(Arow + k0 + j * 4);
        }
        int s = ci0 & 1;
        st_split4(xR, &Xh[s][xr * MALD + xc], &Xl[s][xr * MALD + xc]);
        #pragma unroll
        for (int j = 0; j < 4; j++)
            st_hi4(aR[j], &Ah[s][ar * MALD + ahalf * 16 + j * 4]);
    }

    for (int ci = ci0; ci < ci1; ci++) {
        int s = ci & 1;
        __syncthreads();
        bool more = (ci + 1 < ci1);
        if (more) {
            int k0 = (ci + 1) * MMKC;
            xR = Z4;
            if (k0 + xr < n) xR = *(const float4*)(x + (size_t)(k0 + xr) * 32 + xc);
            #pragma unroll
            for (int j = 0; j < 4; j++) {
                int col = ahalf * 16 + j * 4;
                aR[j] = Z4;
                if (gr < n && (k0 + col + 4) <= n) aR[j] = *(const float4*)(Arow + k0 + j * 4);
            }
        }
        uint32_t aOff = (uint32_t)s * (A_STAGE * 2);
        uint32_t xOff = (uint32_t)s * (X_STAGE * 2);
        #pragma unroll
        for (int ks = 0; ks < MMKC; ks += 16) {
            uint32_t afh[4];
            ldm_x4(afh, aAddrH0 + aOff + ks * 2);
            #pragma unroll
            for (int np = 0; np < 2; np++) {
                uint32_t bh[4], bl[4];
                uint32_t off = (uint32_t)(ks * MALD + np * 16) * 2;
                ldm_x4_t(bh, xBaseH0 + xOff + off);
                ldm_x4_t(bl, xBaseL0 + xOff + off);
                mma_bf16(acc[np * 2 + 0], afh, bh[0], bh[1]);
                mma_bf16(acc[np * 2 + 1], afh, bh[2], bh[3]);
                mma_bf16(acc[np * 2 + 0], afh, bl[0], bl[1]);
                mma_bf16(acc[np * 2 + 1], afh, bl[2], bl[3]);
            }
        }
        if (more) {
            st_split4(xR, &Xh[s^1][xr * MALD + xc], &Xl[s^1][xr * MALD + xc]);
            #pragma unroll
            for (int j = 0; j < 4; j++)
                st_hi4(aR[j], &Ah[s^1][ar * MALD + ahalf * 16 + j * 4]);
        }
    }

    int gr8 = lane >> 2, cc = (lane & 3) * 2;
    #pragma unroll
    for (int f = 0; f < 4; f++) {
        int nc = f * 8 + cc;
        int r0 = m0 + warp * 16 + gr8;
        int r1 = r0 + 8;
        if (r0 < n) red2(y + (size_t)r0 * 32 + nc, acc[f][0], acc[f][1]);
        if (r1 < n) red2(y + (size_t)r1 * 32 + nc, acc[f][2], acc[f][3]);
    }
}

// ---------------- group_userlayer ----------------
__global__ void k_gul(float* __restrict__ gul, const int* __restrict__ users,
                      const float* __restrict__ mask, const float* __restrict__ t0,
                      const float* __restrict__ t1, const float* __restrict__ t2) {
    int i = blockIdx.x * blockDim.x + threadIdx.x;
    if (i >= G_N * 32) return;
    int g = i >> 5, d = i & 31;
    float s = 0.f;
    #pragma unroll
    for (int l = 0; l < LM; l++) {
        int u = __ldg(users + g * LM + l);
        size_t o = ((size_t)u << 5) + d;
        float acc = __ldg(t0 + o) + __ldg(t1 + o) + __ldg(t2 + o);
        s = fmaf(__ldg(mask + g * LM + l), acc, s);
    }
    gul[i] = 0.25f * s;
}

// ---------------- gate MLP ----------------
__global__ void k_gate(float* __restrict__ w, const float* __restrict__ gsum,
                       const float* __restrict__ gl2, const float* __restrict__ gul,
                       const float* __restrict__ w1, const float* __restrict__ b1,
                       const float* __restrict__ w2, const float* __restrict__ b2) {
    int wid = (blockIdx.x * blockDim.x + threadIdx.x) >> 5;
    int lane = threadIdx.x & 31;
    if (wid >= 2 * G_N) return;
    float xd;
    if (wid < G_N) {
        size_t o = (size_t)wid * 32 + lane;
        xd = 0.25f * (__ldg(gsum + o) + __ldg(gl2 + o));
    } else {
        xd = __ldg(gul + (size_t)(wid - G_N) * 32 + lane);
    }
    float h = b1[lane];
    #pragma unroll
    for (int d = 0; d < 32; d++) {
        float a = __shfl_sync(0xffffffffu, xd, d);
        h = fmaf(a, __ldg(w1 + d * 32 + lane), h);
    }
    h = fmaxf(h, 0.f);
    float t = h * __ldg(w2 + lane);
    #pragma unroll
    for (int o = 16; o > 0; o >>= 1) t += __shfl_xor_sync(0xffffffffu, t, o);
    if (lane == 0) w[wid] = 1.f / (1.f + expf(-(t + b2[0])));
}

__global__ void k_combine(float* __restrict__ gf, const float* __restrict__ w,
                          const float* __restrict__ gsum, const float* __restrict__ gl2,
                          const float* __restrict__ gul) {
    int i = blockIdx.x * blockDim.x + threadIdx.x;
    if (i >= G_N * 32) return;
    int g = i >> 5;
    gf[i] = w[g] * 0.25f * (gsum[i] + gl2[i]) + w[G_N + g] * gul[i];
}

// ---------------- predict MLP ----------------
__global__ void k_pred(float* __restrict__ out, const int* __restrict__ gin,
                       const int* __restrict__ iin, const float* __restrict__ gf,
                       const float* __restrict__ t0, const float* __restrict__ t1,
                       const float* __restrict__ t2,
                       const float* __restrict__ pw1, const float* __restrict__ pb1,
                       const float* __restrict__ pw2, const float* __restrict__ pb2) {
    int wid = (blockIdx.x * blockDim.x + threadIdx.x) >> 5;
    int lane = threadIdx.x & 31;
    if (wid >= B_N) return;
    int g = __ldg(gin + wid), it = __ldg(iin + wid);
    size_t o = ((size_t)it << 5) + lane;
    float ia = 0.25f * (__ldg(t0 + o) + __ldg(t1 + o) + __ldg(t2 + o));
    float e = __ldg(gf + (size_t)g * 32 + lane) * ia;
    float s = 0.f;
    #pragma unroll
    for (int j = 0; j < 8; j++) {
        float p = e * __ldg(pw1 + lane * 8 + j);
        #pragma unroll
        for (int o2 = 16; o2 > 0; o2 >>= 1) p += __shfl_xor_sync(0xffffffffu, p, o2);
        s += fmaxf(p + pb1[j], 0.f) * pw2[j];
    }
    if (lane == 0) out[wid] = 1.f / (1.f + expf(-(s + pb2[0])));
}

// ---------------- host driver ----------------
static inline int cdiv(int a, int b) { return (a + b - 1) / b; }

extern "C" void kernel_launch(void* const* d_in, const int* in_sizes, int n_in,
                              void* d_out, int out_size) {
    const int*   gin  = (const int*)  d_in[0];
    const int*   iin  = (const int*)  d_in[1];
    const float* uemb = (const float*)d_in[2];
    const float* gemb = (const float*)d_in[3];
    const float* iemb = (const float*)d_in[4];
    const int*   ui_r = (const int*)  d_in[5];
    const int*   ui_c = (const int*)  d_in[6];
    const float* ui_v = (const float*)d_in[7];
    const int*   gi_r = (const int*)  d_in[8];
    const int*   gi_c = (const int*)  d_in[9];
    const float* gi_v = (const float*)d_in[10];
    const float* ovu  = (const float*)d_in[11];
    const float* ovi  = (const float*)d_in[12];
    const int*   agu  = (const int*)  d_in[13];
    const float* agm  = (const float*)d_in[14];
    const float* gw1  = (const float*)d_in[15];
    const float* gb1  = (const float*)d_in[16];
    const float* gw2  = (const float*)d_in[17];
    const float* gb2  = (const float*)d_in[18];
    const float* pw1  = (const float*)d_in[19];
    const float* pb1  = (const float*)d_in[20];
    const float* pw2  = (const float*)d_in[21];
    const float* pb2  = (const float*)d_in[22];
    float* out = (float*)d_out;
    const int nnz_ui = in_sizes[5];
    const int nnz_gi = in_sizes[8];

    float* S = nullptr;
    cudaGetSymbolAddress((void**)&S, d_scratch);

    const int TPB = 256;
    int spmm_ui_grid = cdiv(nnz_ui * 4, TPB);
    int spmm_gi_grid = cdiv(nnz_gi * 4, TPB);

    cudaStream_t s2;
    cudaStreamCreateWithFlags(&s2, cudaStreamNonBlocking);
    cudaEvent_t evFork, evJoin;
    cudaEventCreateWithFlags(&evFork, cudaEventDisableTiming);
    cudaEventCreateWithFlags(&evJoin, cudaEventDisableTiming);

    // single zero of all accumulation buffers
    k_zero4<<<cdiv(984000,TPB),TPB>>>((float4*)S, 984000);

    // ======== UI graph conv ========
    k_spmm<<<spmm_ui_grid,TPB>>>(ui_r, ui_c, ui_v, nnz_ui, uemb, iemb, U_N,
                                 S + OFF_UI_B, U_N + I_N);
    k_spmm<<<spmm_ui_grid,TPB>>>(ui_r, ui_c, ui_v, nnz_ui,
                                 S + OFF_UI_B, S + OFF_UI_B + U_N*32, U_N,
                                 S + OFF_UI_A, U_N + I_N);
    k_spmm<<<spmm_ui_grid,TPB>>>(ui_r, ui_c, ui_v, nnz_ui,
                                 S + OFF_UI_A, S + OFF_UI_A + U_N*32, U_N,
                                 S + OFF_UI_C, U_N + I_N);
    k_comb_ui<<<cdiv(168000,TPB),TPB>>>(S, (const float4*)uemb,
                                        (const float4*)iemb, (const float4*)gemb);

    // ---- fork: user social MM chain on s2 ----
    cudaEventRecord(evFork, 0);
    cudaStreamWaitEvent(s2, evFork, 0);
    {
        dim3 g(cdiv(U_N, 128), 11);
        k_mm_tc<<<g, 256, 0, s2>>>(ovu, S + OFF_USUM, S + OFF_YS, U_N);
        k_mm_tc<<<g, 256, 0, s2>>>(ovu, S + OFF_YS,   S + OFF_UM, U_N);
    }

    // ======== GI graph conv on stream 0 ========
    k_spmm<<<spmm_gi_grid,TPB>>>(gi_r, gi_c, gi_v, nnz_gi, gemb, S + OFF_IEU, G_N,
                                 S + OFF_GI_B, G_N + I_N);
    k_spmm<<<spmm_gi_grid,TPB>>>(gi_r, gi_c, gi_v, nnz_gi,
                                 S + OFF_GI_B, S + OFF_GI_B + G_N*32, G_N,
                                 S + OFF_GI_A, G_N + I_N);
    k_spmm<<<spmm_gi_grid,TPB>>>(gi_r, gi_c, gi_v, nnz_gi,
                                 S + OFF_GI_A, S + OFF_GI_A + G_N*32, G_N,
                                 S + OFF_GI_C, G_N + I_N);
    k_spmm<<<spmm_gi_grid,TPB>>>(gi_r, gi_c, gi_v, nnz_gi, gemb, iemb, G_N,
                                 S + OFF_GSUM, G_N);
    k_spmm<<<spmm_gi_grid,TPB>>>(gi_r, gi_c, gi_v, nnz_gi, gemb, S + OFF_UI_A + U_N*32,
                                 G_N, S + OFF_GSUM, G_N);
    k_comb_gi<<<cdiv(64000,TPB),TPB>>>(S);

    // ======== item social MM chain on stream 0 ========
    {
        dim3 g(cdiv(I_N, 128), 14);
        k_mm_tc<<<g, 256>>>(ovi, S + OFF_GIIS, S + OFF_YI, I_N);
        k_mm_tc<<<g, 256>>>(ovi, S + OFF_YI,   S + OFF_IM, I_N);
    }

    // ---- join ----
    cudaEventRecord(evJoin, s2);
    cudaStreamWaitEvent(0, evJoin, 0);

    // ======== pooling, gate, predict ========
    k_gul<<<cdiv(G_N*32, TPB), TPB>>>(S + OFF_GUL, agu, agm,
                                      S + OFF_USUM, S + OFF_YS, S + OFF_UM);
    k_gate<<<cdiv(2*G_N*32, TPB), TPB>>>(S + OFF_W, S + OFF_GSUM, S + OFF_GI_A,
                                         S + OFF_GUL, gw1, gb1, gw2, gb2);
    k_combine<<<cdiv(G_N*32, TPB), TPB>>>(S + OFF_GF, S + OFF_W, S + OFF_GSUM,
                                          S + OFF_GI_A, S + OFF_GUL);
    k_pred<<<cdiv(B_N*32, TPB), TPB>>>(out, gin, iin, S + OFF_GF,
                                       S + OFF_GIIS, S + OFF_YI, S + OFF_IM,
                                       pw1, pb1, pw2, pb2);

    cudaEventDestroy(evFork);
    cudaEventDestroy(evJoin);
    cudaStreamDestroy(s2);
}